// round 10
// baseline (speedup 1.0000x reference)
#include <cuda_runtime.h>
#include <cuda_bf16.h>
#include <math.h>
#include <stdint.h>

#define Bb 32
#define Ss 24
#define Tt 24
#define Vv 30000
#define Ee 620
#define Hh 1000
#define Mm 500
#define RS (Ss*Bb)   /* 768 */
#define RT (Tt*Bb)   /* 768 */
#define NBLK 125
#define NCOLS 8

#define K3E 1920
#define K3H 3072
#define K3M 1536

// ---------------- fp32 scratch ----------------
__device__ float g_Xr[RS*Hh];    // [t][j][b]
__device__ float g_Xz[RS*Hh];
__device__ float g_Xc[RS*Hh];
__device__ float g_Yr[RT*Hh];
__device__ float g_Yz[RT*Hh];
__device__ float g_Yc[RT*Hh];
__device__ float g_Yo[RT*Hh];    // normal [row][2M]
__device__ float g_hT2[Hh*Bb];   // paired transposed state
__device__ float g_s0T[Hh*Bb];
__device__ float g_rhT2[Hh*Bb];
__device__ float g_cCrT[Hh*Bb];
__device__ float g_cCzT[Hh*Bb];
__device__ float g_cCT [Hh*Bb];
__device__ float g_cCo[Bb*Hh];
__device__ unsigned g_barctr;

// ---------------- bf16 tripled operands ----------------
__device__ __nv_bfloat16 g3_eWr[Hh*K3E];
__device__ __nv_bfloat16 g3_eWz[Hh*K3E];
__device__ __nv_bfloat16 g3_eW [Hh*K3E];
__device__ __nv_bfloat16 g3_dWr[Hh*K3E];
__device__ __nv_bfloat16 g3_dWz[Hh*K3E];
__device__ __nv_bfloat16 g3_dW [Hh*K3E];
__device__ __nv_bfloat16 g3_Vo [Hh*K3E];
__device__ __nv_bfloat16 g3_Ws [Hh*K3H];
__device__ __nv_bfloat16 g3_Cr [Hh*K3H];
__device__ __nv_bfloat16 g3_Cz [Hh*K3H];
__device__ __nv_bfloat16 g3_C  [Hh*K3H];
__device__ __nv_bfloat16 g3_Co [Hh*K3H];
__device__ __nv_bfloat16 g3_Uo [Hh*K3H];
__device__ __nv_bfloat16 g3_Wo [Vv*K3M];
__device__ __nv_bfloat16 g3_X  [RS*K3E];
__device__ __nv_bfloat16 g3_Y  [RT*K3E];
__device__ __nv_bfloat16 g3_cT [Bb*K3H];
__device__ __nv_bfloat16 g3_S  [RT*K3H];
__device__ __nv_bfloat16 g3_T  [RT*K3M];

__device__ __forceinline__ int ptidx(int j, int b) { return ((j >> 1) * 64) + 2 * b + (j & 1); }

// ---------------- embedding gather fused with bf16 tripling (+ optional state/barrier zeroing) ----------------
__global__ void gather_trip(const int* __restrict__ tok, const float* __restrict__ emb,
                            __nv_bfloat16* __restrict__ out3, int L, int nrows,
                            float* __restrict__ zbuf)
{
    int r = blockIdx.x;
    if (r >= nrows) {
        // zero hT2 (32000 floats) + barrier counter; blocks nrows..nrows+31
        int zb = r - nrows;
        int base = (zb * 128 + threadIdx.x) * 8;
        if (base < Hh * Bb) {
            float4 z4 = {0.f, 0.f, 0.f, 0.f};
            *(float4*)(zbuf + base) = z4;
            *(float4*)(zbuf + base + 4) = z4;
        }
        if (zb == 0 && threadIdx.x == 0) g_barctr = 0;
        return;
    }
    int s = r >> 5, b = r & 31;
    int token = tok[b * L + s];
    const float* srcp = emb + (long)token * Ee;
    __nv_bfloat16* dst = out3 + (size_t)r * K3E;
    for (int e = threadIdx.x; e < Ee; e += blockDim.x) {
        float v = srcp[e];
        __nv_bfloat16 h = __float2bfloat16(v);
        __nv_bfloat16 l = __float2bfloat16(v - __bfloat162float(h));
        dst[e] = h; dst[Ee + e] = l; dst[2 * Ee + e] = h;
    }
}

// ---------------- fp32 -> tripled bf16 convert, flattened multi-entry ----------------
struct ConvEntry { const float* src; __nv_bfloat16* dst; int R, K, K3p, typeB, paired; };
struct ConvBatch14 { ConvEntry e[14]; int blkStart[15]; };

__global__ void conv_all(ConvBatch14 cb)
{
    int blk = blockIdx.x;
    int ei = 0;
    while (blk >= cb.blkStart[ei + 1]) ei++;
    ConvEntry E = cb.e[ei];
    int per = E.K3p >> 3;
    int total = E.R * per;
    int i = (blk - cb.blkStart[ei]) * 256 + threadIdx.x;
    if (i >= total) return;
    int r = i / per, c8 = (i - r * per) * 8;
    const float* s = E.src + (size_t)r * E.K;
    __nv_bfloat16 o[8];
#pragma unroll
    for (int j = 0; j < 8; j++) {
        int k3 = c8 + j;
        int K = E.K;
        float v = 0.f; int wantLo = 0;
        int k = -1;
        if (k3 < K)          { k = k3;         wantLo = 0; }
        else if (k3 < 2 * K) { k = k3 - K;     wantLo = E.typeB ? 0 : 1; }
        else if (k3 < 3 * K) { k = k3 - 2 * K; wantLo = E.typeB ? 1 : 0; }
        if (k >= 0) v = E.paired ? E.src[((k >> 1) << 6) + 2 * r + (k & 1)] : s[k];
        __nv_bfloat16 h = __float2bfloat16(v);
        o[j] = wantLo ? __float2bfloat16(v - __bfloat162float(h)) : h;
    }
    *(float4*)(E.dst + (size_t)r * E.K3p + c8) = *(float4*)o;
}

// ================= bf16 GEMM (cp.async double-buffered) =================
struct MultiGemm {
    const __nv_bfloat16* A3[7];
    const __nv_bfloat16* B3[7];
    void*        C[7];
    const float* bias[7];
    const float* add1[7];
    const float* add2[7];
    int mode[7];
    int M, N, K3p, ldc;
};

#define GBM 128
#define GBN 128
#define GBK 64
#define GSK 72
#define GSTAGE_ELEMS (128*GSK)
#define GSMEM_BYTES (4*GSTAGE_ELEMS*2)

__device__ __forceinline__ uint32_t smem_u32(const void* p) {
    return (uint32_t)__cvta_generic_to_shared(p);
}
__device__ __forceinline__ void ldsm4(uint32_t &r0, uint32_t &r1, uint32_t &r2, uint32_t &r3, uint32_t a) {
    asm volatile("ldmatrix.sync.aligned.m8n8.x4.shared.b16 {%0,%1,%2,%3}, [%4];\n"
        : "=r"(r0), "=r"(r1), "=r"(r2), "=r"(r3) : "r"(a));
}
__device__ __forceinline__ void mma_bf16(float* c, const uint32_t* a, uint32_t b0, uint32_t b1) {
    asm volatile("mma.sync.aligned.m16n8k16.row.col.f32.bf16.bf16.f32 "
        "{%0,%1,%2,%3},{%4,%5,%6,%7},{%8,%9},{%0,%1,%2,%3};\n"
        : "+f"(c[0]), "+f"(c[1]), "+f"(c[2]), "+f"(c[3])
        : "r"(a[0]), "r"(a[1]), "r"(a[2]), "r"(a[3]), "r"(b0), "r"(b1));
}
__device__ __forceinline__ void cpasync16(uint32_t daddr, const void* src, int sbytes) {
    asm volatile("cp.async.cg.shared.global [%0], [%1], 16, %2;\n"
        :: "r"(daddr), "l"(src), "r"(sbytes));
}

__global__ __launch_bounds__(256, 2)
void bf16_gemm(MultiGemm g)
{
    extern __shared__ __nv_bfloat16 smem[];
    __nv_bfloat16* sA = smem;
    __nv_bfloat16* sB = smem + 2 * GSTAGE_ELEMS;

    int z = blockIdx.z;
    const __nv_bfloat16* A  = g.A3[z];
    const __nv_bfloat16* Bm = g.B3[z];
    void* C           = g.C[z];
    const float* bias = g.bias[z];
    const float* add1 = g.add1[z];
    const float* add2 = g.add2[z];
    int mode = g.mode[z];
    int M = g.M, N = g.N, K3p = g.K3p, ldc = g.ldc;

    int t = threadIdx.x, lane = t & 31, wid = t >> 5;
    int wm = wid & 1, wn = wid >> 1;
    int m0 = blockIdx.y * GBM, n0 = blockIdx.x * GBN;

    float acc[4][4][4];
#pragma unroll
    for (int i = 0; i < 4; i++)
#pragma unroll
        for (int j = 0; j < 4; j++)
#pragma unroll
            for (int c = 0; c < 4; c++) acc[i][j][c] = 0.f;

    int sel = lane >> 3, l7 = lane & 7;
    int ar = (sel & 1) * 8 + l7;
    int ac = (sel >> 1) * 8;
    int br = (sel >> 1) * 8 + l7;
    int bc = (sel & 1) * 8;

    int KT = K3p / GBK;

    auto loadStage = [&](int kt, int st) {
        int kbase = kt * GBK;
#pragma unroll
        for (int i = 0; i < 4; i++) {
            int idx = t + i * 256;
            int row = idx >> 3, sg = idx & 7;
            {
                int gr = m0 + row;
                int ok = (gr < M);
                const __nv_bfloat16* src = A + (size_t)(ok ? gr : 0) * K3p + kbase + sg * 8;
                cpasync16(smem_u32(&sA[st * GSTAGE_ELEMS + row * GSK + sg * 8]), src, ok ? 16 : 0);
            }
            {
                int gr = n0 + row;
                int ok = (gr < N);
                const __nv_bfloat16* src = Bm + (size_t)(ok ? gr : 0) * K3p + kbase + sg * 8;
                cpasync16(smem_u32(&sB[st * GSTAGE_ELEMS + row * GSK + sg * 8]), src, ok ? 16 : 0);
            }
        }
        asm volatile("cp.async.commit_group;\n");
    };

    loadStage(0, 0);

    for (int kt = 0; kt < KT; kt++) {
        int st = kt & 1;
        if (kt + 1 < KT) {
            loadStage(kt + 1, st ^ 1);
            asm volatile("cp.async.wait_group 1;\n");
        } else {
            asm volatile("cp.async.wait_group 0;\n");
        }
        __syncthreads();

        const __nv_bfloat16* a_st = sA + st * GSTAGE_ELEMS;
        const __nv_bfloat16* b_st = sB + st * GSTAGE_ELEMS;
#pragma unroll
        for (int kh = 0; kh < 4; kh++) {
            uint32_t af[4][4], bf[4][2];
#pragma unroll
            for (int mi = 0; mi < 4; mi++) {
                uint32_t addr = smem_u32(&a_st[(wm * 64 + mi * 16 + ar) * GSK + kh * 16 + ac]);
                ldsm4(af[mi][0], af[mi][1], af[mi][2], af[mi][3], addr);
            }
#pragma unroll
            for (int p = 0; p < 2; p++) {
                uint32_t r0, r1, r2, r3;
                uint32_t addr = smem_u32(&b_st[(wn * 32 + p * 16 + br) * GSK + kh * 16 + bc]);
                ldsm4(r0, r1, r2, r3, addr);
                bf[2*p][0] = r0; bf[2*p][1] = r1; bf[2*p+1][0] = r2; bf[2*p+1][1] = r3;
            }
#pragma unroll
            for (int mi = 0; mi < 4; mi++)
#pragma unroll
                for (int ni = 0; ni < 4; ni++)
                    mma_bf16(acc[mi][ni], af[mi], bf[ni][0], bf[ni][1]);
        }
        __syncthreads();
    }

    int gq = lane >> 2, tig = lane & 3;
    if (mode == 6) {
        __nv_bfloat16* T = (__nv_bfloat16*)C;
#pragma unroll
        for (int mi = 0; mi < 4; mi++) {
#pragma unroll
            for (int ni = 0; ni < 4; ni++) {
                int colb = n0 + wn * 32 + ni * 8 + tig * 2;
                if (colb >= N) continue;
                int m = colb >> 1;
#pragma unroll
                for (int half = 0; half < 2; half++) {
                    int row = m0 + wm * 64 + mi * 16 + gq + half * 8;
                    if (row >= M) continue;
                    int b = row & 31;
                    float v0 = acc[mi][ni][half * 2 + 0] + add1[(size_t)row * ldc + colb]     + add2[(size_t)b * ldc + colb];
                    float v1 = acc[mi][ni][half * 2 + 1] + add1[(size_t)row * ldc + colb + 1] + add2[(size_t)b * ldc + colb + 1];
                    float vm = fmaxf(v0, v1);
                    __nv_bfloat16 h = __float2bfloat16(vm);
                    __nv_bfloat16 l = __float2bfloat16(vm - __bfloat162float(h));
                    size_t base = (size_t)row * K3M;
                    T[base + m] = h; T[base + Mm + m] = l; T[base + 2 * Mm + m] = h;
                }
            }
        }
        return;
    }
#pragma unroll
    for (int mi = 0; mi < 4; mi++) {
#pragma unroll
        for (int ni = 0; ni < 4; ni++) {
#pragma unroll
            for (int c = 0; c < 4; c++) {
                int row = m0 + wm * 64 + mi * 16 + gq + ((c >> 1) ? 8 : 0);
                int col = n0 + wn * 32 + ni * 8 + tig * 2 + (c & 1);
                if (row >= M || col >= N) continue;
                float v = acc[mi][ni][c];
                if (mode == 0) {
                    if (bias) v += bias[col];
                    ((float*)C)[(size_t)row * ldc + col] = v;
                } else if (mode == 3) {
                    int b = row & 31, ti = row >> 5;
                    ((float*)C)[(size_t)b * (Tt * Vv) + (size_t)ti * Vv + col] = v;
                } else if (mode == 4) {
                    if (bias) v += bias[col];
                    int b = row & 31, ti = row >> 5;
                    ((float*)C)[((size_t)ti * Hh + col) * 32 + b] = v;
                } else { // 5
                    int b = row & 31;
                    float tv = tanhf(v);
                    ((float*)add1)[ptidx(col, b)] = tv;
                    __nv_bfloat16 h = __float2bfloat16(tv);
                    __nv_bfloat16 l = __float2bfloat16(tv - __bfloat162float(h));
                    __nv_bfloat16* S3p = (__nv_bfloat16*)C;
                    size_t base = (size_t)b * K3H;
                    S3p[base + col] = h; S3p[base + Hh + col] = l; S3p[base + 2 * Hh + col] = h;
                }
            }
        }
    }
}

// ================= persistent recurrence =================
__device__ __forceinline__ unsigned long long pack2(float2 v) {
    unsigned long long r;
    asm("mov.b64 %0, {%1, %2};" : "=l"(r) : "f"(v.x), "f"(v.y));
    return r;
}
__device__ __forceinline__ unsigned long long pack2f(float a, float b) {
    unsigned long long r;
    asm("mov.b64 %0, {%1, %2};" : "=l"(r) : "f"(a), "f"(b));
    return r;
}
__device__ __forceinline__ float2 unpack2(unsigned long long v) {
    float2 r;
    asm("mov.b64 {%0, %1}, %2;" : "=f"(r.x), "=f"(r.y) : "l"(v));
    return r;
}
__device__ __forceinline__ void ffma2(unsigned long long &acc, unsigned long long a, unsigned long long b) {
    asm("fma.rn.f32x2 %0, %1, %2, %0;" : "+l"(acc) : "l"(a), "l"(b));
}

// single-counter atomic barrier (R3-proven), epoch-based, no per-launch reset
__device__ __forceinline__ void gbar(unsigned &tgt) {
    __threadfence();
    __syncthreads();
    if (threadIdx.x == 0) {
        atomicAdd(&g_barctr, 1u);
        unsigned v;
        do {
            asm volatile("ld.acquire.gpu.global.u32 %0, [%1];" : "=r"(v) : "l"(&g_barctr) : "memory");
            if (v >= tgt) break;
            __nanosleep(32);
        } while (true);
    }
    __syncthreads();
    tgt += gridDim.x;
}

#define SMEM_RECUR (28352*4)

__global__ __launch_bounds__(256, 1)
void recur_persist(float* __restrict__ hT2, float* __restrict__ rhT2,
    const float* __restrict__ GUr, const float* __restrict__ GUz, const float* __restrict__ GUc,
    const float* __restrict__ Xr, const float* __restrict__ Xz, const float* __restrict__ Xc,
    const float* __restrict__ ctxR, const float* __restrict__ ctxZ, const float* __restrict__ ctxC,
    __nv_bfloat16* __restrict__ S3out, int nsteps, unsigned bbase)
{
    extern __shared__ float sm[];
    float* usr = sm;
    float* usz = sm + 8000;
    float* usc = sm + 16000;
    float* red = sm + 24000;
    float* zs  = sm + 28096;
    int tid = threadIdx.x, lane = tid & 31, w = tid >> 5;
    int jbase = blockIdx.x * NCOLS;

    for (int i4 = tid; i4 < 2000; i4 += 256) {
        int row = i4 / 250, k4 = (i4 % 250) * 4;
        *(float4*)(usr + row * 1000 + k4) = *(const float4*)(GUr + (size_t)(jbase + row) * 1000 + k4);
        *(float4*)(usz + row * 1000 + k4) = *(const float4*)(GUz + (size_t)(jbase + row) * 1000 + k4);
        *(float4*)(usc + row * 1000 + k4) = *(const float4*)(GUc + (size_t)(jbase + row) * 1000 + k4);
    }
    __syncthreads();

    // per-warp kk2 slices; all lens multiple of 4 for chunk-4 double buffering
    const int offs[8] = {0, 64, 128, 192, 256, 320, 380, 440};
    const int lens[8] = {64, 64, 64, 64, 64, 60, 60, 60};
    int off = offs[w], len = lens[w];
    unsigned tgt = bbase + gridDim.x;

    for (int step = 0; step < nsteps; step++) {
        // ---------- phase A: r,z gates ----------
        {
            unsigned long long acc[16];
#pragma unroll
            for (int p = 0; p < 16; p++) acc[p] = 0ull;
            float2 cur[4], nxt[4];
#pragma unroll
            for (int q = 0; q < 4; q++) cur[q] = *(const float2*)(hT2 + (off + q) * 64 + 2 * lane);
            for (int base = 0; base < len; base += 4) {
                if (base + 4 < len) {
#pragma unroll
                    for (int q = 0; q < 4; q++)
                        nxt[q] = *(const float2*)(hT2 + (off + base + 4 + q) * 64 + 2 * lane);
                }
#pragma unroll
                for (int q2 = 0; q2 < 4; q2 += 2) {
                    int k0 = (off + base + q2) * 2;
                    unsigned long long h0p = pack2(cur[q2]), h1p = pack2(cur[q2 + 1]);
#pragma unroll
                    for (int p = 0; p < 16; p++) {
                        const float* us = (p & 1) ? usz : usr;
                        float4 u = *(const float4*)(us + (p >> 1) * 1000 + k0);
                        ffma2(acc[p], h0p, pack2f(u.x, u.y));
                        ffma2(acc[p], h1p, pack2f(u.z, u.w));
                    }
                }
#pragma unroll
                for (int q = 0; q < 4; q++) cur[q] = nxt[q];
            }
#pragma unroll
            for (int p = 0; p < 16; p++) {
                float2 a = unpack2(acc[p]);
                red[w * 512 + p * 32 + lane] = a.x + a.y;
            }
            __syncthreads();
            for (int o = tid; o < 512; o += 256) {
                int p = o >> 5, b = o & 31;
                int col = p >> 1, gate = p & 1;
                int jg = jbase + col;
                float s = 0.f;
#pragma unroll
                for (int ww = 0; ww < 8; ww++) s += red[ww * 512 + p * 32 + b];
                const float* X = gate ? Xz : Xr;
                float pre = X[((size_t)step * Hh + jg) * 32 + b] + s;
                const float* ctx = gate ? ctxZ : ctxR;
                if (ctx) pre += ctx[jg * 32 + b];
                float sg = 1.f / (1.f + __expf(-pre));
                if (gate == 0) {
                    int hi = ptidx(jg, b);
                    rhT2[hi] = sg * hT2[hi];
                } else {
                    zs[col * 32 + b] = sg;
                }
            }
        }
        gbar(tgt);
        // ---------- phase B: candidate + blend ----------
        {
            unsigned long long acc[8];
#pragma unroll
            for (int p = 0; p < 8; p++) acc[p] = 0ull;
            float2 cur[4], nxt[4];
#pragma unroll
            for (int q = 0; q < 4; q++) cur[q] = *(const float2*)(rhT2 + (off + q) * 64 + 2 * lane);
            for (int base = 0; base < len; base += 4) {
                if (base + 4 < len) {
#pragma unroll
                    for (int q = 0; q < 4; q++)
                        nxt[q] = *(const float2*)(rhT2 + (off + base + 4 + q) * 64 + 2 * lane);
                }
#pragma unroll
                for (int q2 = 0; q2 < 4; q2 += 2) {
                    int k0 = (off + base + q2) * 2;
                    unsigned long long h0p = pack2(cur[q2]), h1p = pack2(cur[q2 + 1]);
#pragma unroll
                    for (int p = 0; p < 8; p++) {
                        float4 u = *(const float4*)(usc + p * 1000 + k0);
                        ffma2(acc[p], h0p, pack2f(u.x, u.y));
                        ffma2(acc[p], h1p, pack2f(u.z, u.w));
                    }
                }
#pragma unroll
                for (int q = 0; q < 4; q++) cur[q] = nxt[q];
            }
            __syncthreads();
#pragma unroll
            for (int p = 0; p < 8; p++) {
                float2 a = unpack2(acc[p]);
                red[w * 256 + p * 32 + lane] = a.x + a.y;
            }
            __syncthreads();
            {
                int col = tid >> 5, b = tid & 31;
                int jg = jbase + col;
                float s = 0.f;
#pragma unroll
                for (int ww = 0; ww < 8; ww++) s += red[ww * 256 + col * 32 + b];
                float pre = Xc[((size_t)step * Hh + jg) * 32 + b] + s;
                if (ctxC) pre += ctxC[jg * 32 + b];
                float cand = tanhf(pre);
                float zv = zs[col * 32 + b];
                int hi = ptidx(jg, b);
                float hv = hT2[hi];
                float hn = (1.f - zv) * hv + zv * cand;
                hT2[hi] = hn;
                if (S3out != nullptr && step + 1 < nsteps) {
                    __nv_bfloat16 h = __float2bfloat16(hn);
                    __nv_bfloat16 l = __float2bfloat16(hn - __bfloat162float(h));
                    size_t base = ((size_t)(step + 1) * 32 + b) * K3H;
                    S3out[base + jg] = h; S3out[base + Hh + jg] = l; S3out[base + 2 * Hh + jg] = h;
                }
            }
        }
        gbar(tgt);
    }
}

// ---------------- host orchestration ----------------
extern "C" void kernel_launch(void* const* d_in, const int* in_sizes, int n_in,
                              void* d_out, int out_size)
{
    const int*   src     = (const int*)d_in[0];
    const int*   tgt     = (const int*)d_in[1];
    const float* src_emb = (const float*)d_in[3];
    const float* tgt_emb = (const float*)d_in[4];
    const float* enc_W   = (const float*)d_in[5];
    const float* enc_Wz  = (const float*)d_in[6];
    const float* enc_Wr  = (const float*)d_in[7];
    const float* enc_U   = (const float*)d_in[8];
    const float* enc_Uz  = (const float*)d_in[9];
    const float* enc_Ur  = (const float*)d_in[10];
    const float* enc_b   = (const float*)d_in[11];
    const float* enc_bz  = (const float*)d_in[12];
    const float* enc_br  = (const float*)d_in[13];
    const float* dec_W   = (const float*)d_in[14];
    const float* dec_Wz  = (const float*)d_in[15];
    const float* dec_Wr  = (const float*)d_in[16];
    const float* dec_U   = (const float*)d_in[17];
    const float* dec_Uz  = (const float*)d_in[18];
    const float* dec_Ur  = (const float*)d_in[19];
    const float* dec_C   = (const float*)d_in[20];
    const float* dec_Cz  = (const float*)d_in[21];
    const float* dec_Cr  = (const float*)d_in[22];
    const float* dec_b   = (const float*)d_in[23];
    const float* dec_bz  = (const float*)d_in[24];
    const float* dec_br  = (const float*)d_in[25];
    const float* W_s     = (const float*)d_in[26];
    const float* U_o     = (const float*)d_in[27];
    const float* V_o     = (const float*)d_in[28];
    const float* C_o     = (const float*)d_in[29];
    const float* W_o     = (const float*)d_in[30];
    float* out = (float*)d_out;

    float *Xr, *Xz, *Xc, *Yr, *Yz, *Yc, *Yo;
    float *hT2, *s0T, *rhT2, *cCrT, *cCzT, *cCT, *cCo;
    cudaGetSymbolAddress((void**)&Xr, g_Xr);
    cudaGetSymbolAddress((void**)&Xz, g_Xz);
    cudaGetSymbolAddress((void**)&Xc, g_Xc);
    cudaGetSymbolAddress((void**)&Yr, g_Yr);
    cudaGetSymbolAddress((void**)&Yz, g_Yz);
    cudaGetSymbolAddress((void**)&Yc, g_Yc);
    cudaGetSymbolAddress((void**)&Yo, g_Yo);
    cudaGetSymbolAddress((void**)&hT2, g_hT2);
    cudaGetSymbolAddress((void**)&s0T, g_s0T);
    cudaGetSymbolAddress((void**)&rhT2, g_rhT2);
    cudaGetSymbolAddress((void**)&cCrT, g_cCrT);
    cudaGetSymbolAddress((void**)&cCzT, g_cCzT);
    cudaGetSymbolAddress((void**)&cCT,  g_cCT);
    cudaGetSymbolAddress((void**)&cCo, g_cCo);

    __nv_bfloat16 *eWr3, *eWz3, *eW3, *dWr3, *dWz3, *dW3, *Vo3;
    __nv_bfloat16 *Ws3, *Cr3, *Cz3, *C3, *Co3, *Uo3, *Wo3;
    __nv_bfloat16 *X3, *Y3, *cT3, *S3, *T3;
    cudaGetSymbolAddress((void**)&eWr3, g3_eWr);
    cudaGetSymbolAddress((void**)&eWz3, g3_eWz);
    cudaGetSymbolAddress((void**)&eW3,  g3_eW);
    cudaGetSymbolAddress((void**)&dWr3, g3_dWr);
    cudaGetSymbolAddress((void**)&dWz3, g3_dWz);
    cudaGetSymbolAddress((void**)&dW3,  g3_dW);
    cudaGetSymbolAddress((void**)&Vo3,  g3_Vo);
    cudaGetSymbolAddress((void**)&Ws3,  g3_Ws);
    cudaGetSymbolAddress((void**)&Cr3,  g3_Cr);
    cudaGetSymbolAddress((void**)&Cz3,  g3_Cz);
    cudaGetSymbolAddress((void**)&C3,   g3_C);
    cudaGetSymbolAddress((void**)&Co3,  g3_Co);
    cudaGetSymbolAddress((void**)&Uo3,  g3_Uo);
    cudaGetSymbolAddress((void**)&Wo3,  g3_Wo);
    cudaGetSymbolAddress((void**)&X3,   g3_X);
    cudaGetSymbolAddress((void**)&Y3,   g3_Y);
    cudaGetSymbolAddress((void**)&cT3,  g3_cT);
    cudaGetSymbolAddress((void**)&S3,   g3_S);
    cudaGetSymbolAddress((void**)&T3,   g3_T);

    cudaFuncSetAttribute(recur_persist, cudaFuncAttributeMaxDynamicSharedMemorySize, SMEM_RECUR);
    cudaFuncSetAttribute(bf16_gemm, cudaFuncAttributeMaxDynamicSharedMemorySize, GSMEM_BYTES);

    // ---- launch 1: all weight converts (flattened) ----
    {
        ConvBatch14 cb = {};
        const float* s[14] = {enc_Wr, enc_Wz, enc_W, dec_Wr, dec_Wz, dec_W, V_o,
                              W_s, dec_Cr, dec_Cz, dec_C, C_o, U_o, W_o};
        __nv_bfloat16* d[14] = {eWr3, eWz3, eW3, dWr3, dWz3, dW3, Vo3,
                                Ws3, Cr3, Cz3, C3, Co3, Uo3, Wo3};
        int acc = 0;
        cb.blkStart[0] = 0;
        for (int i = 0; i < 14; i++) {
            int R = (i < 7) ? Hh : ((i == 13) ? Vv : Hh);
            int K = (i < 7) ? Ee : ((i == 13) ? Mm : Hh);
            int K3p = (i < 7) ? K3E : ((i == 13) ? K3M : K3H);
            cb.e[i] = {s[i], d[i], R, K, K3p, 1, 0};
            int total = R * (K3p / 8);
            acc += (total + 255) / 256;
            cb.blkStart[i + 1] = acc;
        }
        conv_all<<<acc, 256>>>(cb);
    }

    // ---- launches 2,3: gathers (X gather also zeroes hT2 + barrier ctr) ----
    gather_trip<<<RS + 32, 128>>>(src, src_emb, X3, Ss, RS, hT2);
    gather_trip<<<RT, 128>>>(tgt, tgt_emb, Y3, Tt, RT, nullptr);

    // ---- launch 4: all 7 input projections in one z-batched launch ----
    {
        MultiGemm g = {};
        g.M = RS; g.N = Hh; g.K3p = K3E; g.ldc = Hh;
        g.A3[0] = X3; g.B3[0] = eWr3; g.C[0] = Xr; g.bias[0] = enc_br; g.mode[0] = 4;
        g.A3[1] = X3; g.B3[1] = eWz3; g.C[1] = Xz; g.bias[1] = enc_bz; g.mode[1] = 4;
        g.A3[2] = X3; g.B3[2] = eW3;  g.C[2] = Xc; g.bias[2] = enc_b;  g.mode[2] = 4;
        g.A3[3] = Y3; g.B3[3] = dWr3; g.C[3] = Yr; g.bias[3] = dec_br; g.mode[3] = 4;
        g.A3[4] = Y3; g.B3[4] = dWz3; g.C[4] = Yz; g.bias[4] = dec_bz; g.mode[4] = 4;
        g.A3[5] = Y3; g.B3[5] = dW3;  g.C[5] = Yc; g.bias[5] = dec_b;  g.mode[5] = 4;
        g.A3[6] = Y3; g.B3[6] = Vo3;  g.C[6] = Yo; g.bias[6] = nullptr; g.mode[6] = 0;
        dim3 gr((Hh + GBN - 1) / GBN, (RS + GBM - 1) / GBM, 7);
        bf16_gemm<<<gr, 256, GSMEM_BYTES>>>(g);
    }

    // ---- launch 5: encoder recurrence (profiled by ncu -s 5) ----
    recur_persist<<<NBLK, 256, SMEM_RECUR>>>(hT2, rhT2,
        enc_Ur, enc_Uz, enc_U, Xr, Xz, Xc,
        nullptr, nullptr, nullptr, nullptr, Ss, 0);

    // ---- launch 6: cT convert ----
    {
        ConvBatch14 cb = {};
        cb.e[0] = {hT2, cT3, Bb, Hh, K3H, 0, 1};
        int total = Bb * (K3H / 8);
        cb.blkStart[0] = 0;
        cb.blkStart[1] = (total + 255) / 256;
        for (int i = 1; i < 14; i++) cb.blkStart[i + 1] = cb.blkStart[1];
        conv_all<<<cb.blkStart[1], 256>>>(cb);
    }
    // ---- launch 7: context projections ----
    {
        MultiGemm g = {};
        g.M = Bb; g.N = Hh; g.K3p = K3H; g.ldc = Hh;
        for (int i = 0; i < 5; i++) g.A3[i] = cT3;
        g.B3[0] = Ws3; g.C[0] = S3;   g.add1[0] = s0T; g.mode[0] = 5;
        g.B3[1] = Cr3; g.C[1] = cCrT; g.mode[1] = 4;
        g.B3[2] = Cz3; g.C[2] = cCzT; g.mode[2] = 4;
        g.B3[3] = C3;  g.C[3] = cCT;  g.mode[3] = 4;
        g.B3[4] = Co3; g.C[4] = cCo;  g.mode[4] = 0;
        dim3 gr((Hh + GBN - 1) / GBN, 1, 5);
        bf16_gemm<<<gr, 256, GSMEM_BYTES>>>(g);
    }

    // ---- launch 8: decoder recurrence (epoch base continues from encoder) ----
    recur_persist<<<NBLK, 256, SMEM_RECUR>>>(s0T, rhT2,
        dec_Ur, dec_Uz, dec_U, Yr, Yz, Yc,
        cCrT, cCzT, cCT, S3, Tt, (unsigned)(Ss * 2 * NBLK));

    // ---- launch 9: tfull + maxout + tripling (mode 6) ----
    {
        MultiGemm g = {};
        g.M = RT; g.N = Hh; g.K3p = K3H; g.ldc = Hh;
        g.A3[0] = S3; g.B3[0] = Uo3; g.C[0] = T3; g.add1[0] = Yo; g.add2[0] = cCo; g.mode[0] = 6;
        dim3 gr((Hh + GBN - 1) / GBN, (RT + GBM - 1) / GBM, 1);
        bf16_gemm<<<gr, 256, GSMEM_BYTES>>>(g);
    }
    // ---- launch 10: logits ----
    {
        MultiGemm g = {};
        g.M = RT; g.N = Vv; g.K3p = K3M; g.ldc = Vv;
        g.A3[0] = T3; g.B3[0] = Wo3; g.C[0] = out; g.mode[0] = 3;
        dim3 gr((Vv + GBN - 1) / GBN, (RT + GBM - 1) / GBM, 1);
        bf16_gemm<<<gr, 256, GSMEM_BYTES>>>(g);
    }
}

// round 13
// speedup vs baseline: 1.6919x; 1.6919x over previous
#include <cuda_runtime.h>
#include <cuda_fp16.h>
#include <math.h>
#include <stdint.h>

#define Bb 32
#define Ss 24
#define Tt 24
#define Vv 30000
#define Ee 620
#define Hh 1000
#define Mm 500
#define RS (Ss*Bb)   /* 768 */
#define RT (Tt*Bb)   /* 768 */
#define NBLK 125
#define NCOLS 8

#define K2E 1280   /* 2*620=1240 -> pad 1280 */
#define K2H 2048   /* 2*1000=2000 -> pad 2048 */
#define K2M 1024   /* 2*500=1000 -> pad 1024 */

// ---------------- fp32 scratch ----------------
__device__ float g_Xr[RS*Hh];    // [t][j][b]
__device__ float g_Xz[RS*Hh];
__device__ float g_Xc[RS*Hh];
__device__ float g_Yr[RT*Hh];
__device__ float g_Yz[RT*Hh];
__device__ float g_Yc[RT*Hh];
__device__ float g_Yo[RT*Hh];    // normal [row][2M]
__device__ float g_hT2[Hh*Bb];   // paired transposed state
__device__ float g_s0T[Hh*Bb];
__device__ float g_rhT2[Hh*Bb];
__device__ float g_cCrT[Hh*Bb];
__device__ float g_cCzT[Hh*Bb];
__device__ float g_cCT [Hh*Bb];
__device__ float g_cCo[Bb*Hh];
__device__ float g_S[RT*Hh];     // decoder pre-update states [t*32+b][H]
__device__ float g_tfull[RT*Hh];
__device__ float g_tmax[RT*Mm];
__device__ unsigned g_barctr;

// ---------------- fp16 doubled operands (A: [hi|lo], B: [hi|hi]) ----------------
__device__ __half g2_eWr[Hh*K2E];
__device__ __half g2_eWz[Hh*K2E];
__device__ __half g2_eW [Hh*K2E];
__device__ __half g2_dWr[Hh*K2E];
__device__ __half g2_dWz[Hh*K2E];
__device__ __half g2_dW [Hh*K2E];
__device__ __half g2_Vo [Hh*K2E];
__device__ __half g2_Ws [Hh*K2H];
__device__ __half g2_Cr [Hh*K2H];
__device__ __half g2_Cz [Hh*K2H];
__device__ __half g2_C  [Hh*K2H];
__device__ __half g2_Co [Hh*K2H];
__device__ __half g2_Uo [Hh*K2H];
__device__ __half g2_Wo [Vv*K2M];
__device__ __half g2_X  [RS*K2E];
__device__ __half g2_Y  [RT*K2E];
__device__ __half g2_cT [Bb*K2H];
__device__ __half g2_S  [RT*K2H];
__device__ __half g2_T  [RT*K2M];

__device__ __forceinline__ int ptidx(int j, int b) { return ((j >> 1) * 64) + 2 * b + (j & 1); }

// ---------------- embedding gather fused with fp16 doubling (A layout: hi|lo) ----------------
__global__ void gather_trip(const int* __restrict__ tok, const float* __restrict__ emb,
                            __half* __restrict__ out2, int L)
{
    int r = blockIdx.x;
    int s = r >> 5, b = r & 31;
    int token = tok[b * L + s];
    const float* srcp = emb + (long)token * Ee;
    __half* dst = out2 + (size_t)r * K2E;
    for (int e = threadIdx.x; e < Ee; e += blockDim.x) {
        float v = srcp[e];
        __half h = __float2half(v);
        __half l = __float2half(v - __half2float(h));
        dst[e] = h; dst[Ee + e] = l;
    }
    // pad [2*Ee, K2E) stays zero (zero-initialized device global)
}

// ---------------- fp32 -> doubled fp16 convert ----------------
// typeB=1 (B operand): [hi | hi];  typeB=0 (A operand): [hi | lo]
struct ConvEntry { const float* src; __half* dst; int R, K, K2p, typeB, paired; };
struct ConvBatch { ConvEntry e[8]; };

__global__ void conv_k(ConvBatch cb)
{
    ConvEntry E = cb.e[blockIdx.y];
    int per = E.K2p >> 3;
    int total = E.R * per;
    int i = blockIdx.x * 256 + threadIdx.x;
    if (i >= total) return;
    int r = i / per, c8 = (i - r * per) * 8;
    const float* s = E.src + (size_t)r * E.K;
    __half o[8];
#pragma unroll
    for (int j = 0; j < 8; j++) {
        int k2 = c8 + j;
        int K = E.K;
        float v = 0.f; int wantLo = 0;
        int k = -1;
        if (k2 < K)          { k = k2;     wantLo = 0; }
        else if (k2 < 2 * K) { k = k2 - K; wantLo = E.typeB ? 0 : 1; }
        if (k >= 0) v = E.paired ? E.src[((k >> 1) << 6) + 2 * r + (k & 1)] : s[k];
        __half h = __float2half(v);
        o[j] = wantLo ? __float2half(v - __half2float(h)) : h;
    }
    *(float4*)(E.dst + (size_t)r * E.K2p + c8) = *(float4*)o;
}

// ================= fp16 GEMM (cp.async double-buffered) =================
// C = A2 @ B2^T over doubled-K.  blockIdx.z selects instance.
// modes: 0: C[row*ldc+col] (+bias)
//        2: + add1[row*ldc+col] + add2[(row&31)*ldc+col]
//        3: logits scatter C[(row&31)*T*V + (row>>5)*V + col]
//        4: trans-flat C[((row>>5)*Hh + col)*32 + (row&31)] (+bias)
//        5: dual tanh: C[(row&31)*Hh+col]=tanh(v), add1[ptidx(col,row&31)]=tanh(v)
struct MultiGemm {
    const __half* A2;
    const __half* B2[5];
    float*       C[5];
    const float* bias[5];
    const float* add1[5];
    const float* add2[5];
    int mode[5];
    int M, N, K2p, ldc;
};

#define GBM 128
#define GBN 128
#define GBK 64
#define GSK 72
#define GSTAGE_ELEMS (128*GSK)
#define GSMEM_BYTES (4*GSTAGE_ELEMS*2)

__device__ __forceinline__ uint32_t smem_u32(const void* p) {
    return (uint32_t)__cvta_generic_to_shared(p);
}
__device__ __forceinline__ void ldsm4(uint32_t &r0, uint32_t &r1, uint32_t &r2, uint32_t &r3, uint32_t a) {
    asm volatile("ldmatrix.sync.aligned.m8n8.x4.shared.b16 {%0,%1,%2,%3}, [%4];\n"
        : "=r"(r0), "=r"(r1), "=r"(r2), "=r"(r3) : "r"(a));
}
__device__ __forceinline__ void mma_f16(float* c, const uint32_t* a, uint32_t b0, uint32_t b1) {
    asm volatile("mma.sync.aligned.m16n8k16.row.col.f32.f16.f16.f32 "
        "{%0,%1,%2,%3},{%4,%5,%6,%7},{%8,%9},{%0,%1,%2,%3};\n"
        : "+f"(c[0]), "+f"(c[1]), "+f"(c[2]), "+f"(c[3])
        : "r"(a[0]), "r"(a[1]), "r"(a[2]), "r"(a[3]), "r"(b0), "r"(b1));
}
__device__ __forceinline__ void cpasync16(uint32_t daddr, const void* src, int sbytes) {
    asm volatile("cp.async.cg.shared.global [%0], [%1], 16, %2;\n"
        :: "r"(daddr), "l"(src), "r"(sbytes));
}

__global__ __launch_bounds__(256, 2)
void bf16_gemm(MultiGemm g)
{
    extern __shared__ __half smem[];
    __half* sA = smem;
    __half* sB = smem + 2 * GSTAGE_ELEMS;

    int z = blockIdx.z;
    const __half* A  = g.A2;
    const __half* Bm = g.B2[z];
    float* C          = g.C[z];
    const float* bias = g.bias[z];
    const float* add1 = g.add1[z];
    const float* add2 = g.add2[z];
    int mode = g.mode[z];
    int M = g.M, N = g.N, K2p = g.K2p, ldc = g.ldc;

    int t = threadIdx.x, lane = t & 31, wid = t >> 5;
    int wm = wid & 1, wn = wid >> 1;
    int m0 = blockIdx.y * GBM, n0 = blockIdx.x * GBN;

    float acc[4][4][4];
#pragma unroll
    for (int i = 0; i < 4; i++)
#pragma unroll
        for (int j = 0; j < 4; j++)
#pragma unroll
            for (int c = 0; c < 4; c++) acc[i][j][c] = 0.f;

    int sel = lane >> 3, l7 = lane & 7;
    int ar = (sel & 1) * 8 + l7;
    int ac = (sel >> 1) * 8;
    int br = (sel >> 1) * 8 + l7;
    int bc = (sel & 1) * 8;

    int KT = K2p / GBK;

    auto loadStage = [&](int kt, int st) {
        int kbase = kt * GBK;
#pragma unroll
        for (int i = 0; i < 4; i++) {
            int idx = t + i * 256;
            int row = idx >> 3, sg = idx & 7;
            {
                int gr = m0 + row;
                int ok = (gr < M);
                const __half* src = A + (size_t)(ok ? gr : 0) * K2p + kbase + sg * 8;
                cpasync16(smem_u32(&sA[st * GSTAGE_ELEMS + row * GSK + sg * 8]), src, ok ? 16 : 0);
            }
            {
                int gr = n0 + row;
                int ok = (gr < N);
                const __half* src = Bm + (size_t)(ok ? gr : 0) * K2p + kbase + sg * 8;
                cpasync16(smem_u32(&sB[st * GSTAGE_ELEMS + row * GSK + sg * 8]), src, ok ? 16 : 0);
            }
        }
        asm volatile("cp.async.commit_group;\n");
    };

    loadStage(0, 0);

    for (int kt = 0; kt < KT; kt++) {
        int st = kt & 1;
        if (kt + 1 < KT) {
            loadStage(kt + 1, st ^ 1);
            asm volatile("cp.async.wait_group 1;\n");
        } else {
            asm volatile("cp.async.wait_group 0;\n");
        }
        __syncthreads();

        const __half* a_st = sA + st * GSTAGE_ELEMS;
        const __half* b_st = sB + st * GSTAGE_ELEMS;
#pragma unroll
        for (int kh = 0; kh < 4; kh++) {
            uint32_t af[4][4], bf[4][2];
#pragma unroll
            for (int mi = 0; mi < 4; mi++) {
                uint32_t addr = smem_u32(&a_st[(wm * 64 + mi * 16 + ar) * GSK + kh * 16 + ac]);
                ldsm4(af[mi][0], af[mi][1], af[mi][2], af[mi][3], addr);
            }
#pragma unroll
            for (int p = 0; p < 2; p++) {
                uint32_t r0, r1, r2, r3;
                uint32_t addr = smem_u32(&b_st[(wn * 32 + p * 16 + br) * GSK + kh * 16 + bc]);
                ldsm4(r0, r1, r2, r3, addr);
                bf[2*p][0] = r0; bf[2*p][1] = r1; bf[2*p+1][0] = r2; bf[2*p+1][1] = r3;
            }
#pragma unroll
            for (int mi = 0; mi < 4; mi++)
#pragma unroll
                for (int ni = 0; ni < 4; ni++)
                    mma_f16(acc[mi][ni], af[mi], bf[ni][0], bf[ni][1]);
        }
        __syncthreads();
    }

    int gq = lane >> 2, tig = lane & 3;
#pragma unroll
    for (int mi = 0; mi < 4; mi++) {
#pragma unroll
        for (int ni = 0; ni < 4; ni++) {
#pragma unroll
            for (int c = 0; c < 4; c++) {
                int row = m0 + wm * 64 + mi * 16 + gq + ((c >> 1) ? 8 : 0);
                int col = n0 + wn * 32 + ni * 8 + tig * 2 + (c & 1);
                if (row >= M || col >= N) continue;
                float v = acc[mi][ni][c];
                if (mode == 0) {
                    if (bias) v += bias[col];
                    C[(size_t)row * ldc + col] = v;
                } else if (mode == 2) {
                    v += add1[(size_t)row * ldc + col] + add2[(size_t)(row & 31) * ldc + col];
                    C[(size_t)row * ldc + col] = v;
                } else if (mode == 3) {
                    int b = row & 31, ti = row >> 5;
                    C[(size_t)b * (Tt * Vv) + (size_t)ti * Vv + col] = v;
                } else if (mode == 4) {
                    if (bias) v += bias[col];
                    int b = row & 31, ti = row >> 5;
                    C[((size_t)ti * Hh + col) * 32 + b] = v;
                } else { // 5
                    int b = row & 31;
                    float tv = tanhf(v);
                    C[(size_t)b * Hh + col] = tv;
                    ((float*)add1)[ptidx(col, b)] = tv;
                }
            }
        }
    }
}

// ---------------- maxout ----------------
__global__ void maxout_k(const float* __restrict__ tf, float* __restrict__ tm)
{
    int i = blockIdx.x * blockDim.x + threadIdx.x;
    int total = RT * Mm;
    if (i < total) {
        int r = i / Mm, m = i - r * Mm;
        tm[i] = fmaxf(tf[r * Hh + 2 * m], tf[r * Hh + 2 * m + 1]);
    }
}

// ================= persistent recurrence (1706-proven) =================
__device__ __forceinline__ unsigned long long pack2(float2 v) {
    unsigned long long r;
    asm("mov.b64 %0, {%1, %2};" : "=l"(r) : "f"(v.x), "f"(v.y));
    return r;
}
__device__ __forceinline__ unsigned long long pack2f(float a, float b) {
    unsigned long long r;
    asm("mov.b64 %0, {%1, %2};" : "=l"(r) : "f"(a), "f"(b));
    return r;
}
__device__ __forceinline__ float2 unpack2(unsigned long long v) {
    float2 r;
    asm("mov.b64 {%0, %1}, %2;" : "=f"(r.x), "=f"(r.y) : "l"(v));
    return r;
}
__device__ __forceinline__ void ffma2(unsigned long long &acc, unsigned long long a, unsigned long long b) {
    asm("fma.rn.f32x2 %0, %1, %2, %0;" : "+l"(acc) : "l"(a), "l"(b));
}

__device__ __forceinline__ void gbar(unsigned &tgt) {
    __threadfence();
    __syncthreads();
    if (threadIdx.x == 0) {
        atomicAdd(&g_barctr, 1u);
        unsigned v;
        do {
            asm volatile("ld.acquire.gpu.global.u32 %0, [%1];" : "=r"(v) : "l"(&g_barctr) : "memory");
            if (v >= tgt) break;
            __nanosleep(16);
        } while (true);
    }
    __syncthreads();
    tgt += gridDim.x;
}

#define SMEM_RECUR (28352*4)

__global__ __launch_bounds__(256, 1)
void recur_persist(float* __restrict__ hT2, float* __restrict__ rhT2,
    const float* __restrict__ GUr, const float* __restrict__ GUz, const float* __restrict__ GUc,
    const float* __restrict__ Xr, const float* __restrict__ Xz, const float* __restrict__ Xc,
    const float* __restrict__ ctxR, const float* __restrict__ ctxZ, const float* __restrict__ ctxC,
    float* __restrict__ Sst, int nsteps)
{
    extern __shared__ float sm[];
    float* usr = sm;
    float* usz = sm + 8000;
    float* usc = sm + 16000;
    float* red = sm + 24000;
    float* zs  = sm + 28096;
    int tid = threadIdx.x, lane = tid & 31, w = tid >> 5;
    int jbase = blockIdx.x * NCOLS;

    for (int i4 = tid; i4 < 2000; i4 += 256) {
        int row = i4 / 250, k4 = (i4 % 250) * 4;
        *(float4*)(usr + row * 1000 + k4) = *(const float4*)(GUr + (size_t)(jbase + row) * 1000 + k4);
        *(float4*)(usz + row * 1000 + k4) = *(const float4*)(GUz + (size_t)(jbase + row) * 1000 + k4);
        *(float4*)(usc + row * 1000 + k4) = *(const float4*)(GUc + (size_t)(jbase + row) * 1000 + k4);
    }
    __syncthreads();

    const int offs[8] = {0, 64, 128, 192, 256, 318, 380, 440};
    const int lens[8] = {64, 64, 64, 64, 62, 62, 60, 60};
    int off = offs[w], len = lens[w];
    unsigned tgt = gridDim.x;

    for (int step = 0; step < nsteps; step++) {
        // ---------- phase A: r,z gates ----------
        {
            unsigned long long acc[16];
#pragma unroll
            for (int p = 0; p < 16; p++) acc[p] = 0ull;
            float2 h0 = *(const float2*)(hT2 + (off) * 64 + 2 * lane);
            float2 h1 = *(const float2*)(hT2 + (off + 1) * 64 + 2 * lane);
            for (int i = 0; i < len; i += 2) {
                float2 n0, n1;
                if (i + 2 < len) {
                    n0 = *(const float2*)(hT2 + (off + i + 2) * 64 + 2 * lane);
                    n1 = *(const float2*)(hT2 + (off + i + 3) * 64 + 2 * lane);
                }
                int k0 = (off + i) * 2;
                unsigned long long h0p = pack2(h0), h1p = pack2(h1);
#pragma unroll
                for (int p = 0; p < 16; p++) {
                    const float* us = (p & 1) ? usz : usr;
                    float4 u = *(const float4*)(us + (p >> 1) * 1000 + k0);
                    ffma2(acc[p], h0p, pack2f(u.x, u.y));
                    ffma2(acc[p], h1p, pack2f(u.z, u.w));
                }
                h0 = n0; h1 = n1;
            }
#pragma unroll
            for (int p = 0; p < 16; p++) {
                float2 a = unpack2(acc[p]);
                red[w * 512 + p * 32 + lane] = a.x + a.y;
            }
            __syncthreads();
            for (int o = tid; o < 512; o += 256) {
                int p = o >> 5, b = o & 31;
                int col = p >> 1, gate = p & 1;
                int jg = jbase + col;
                float s = 0.f;
#pragma unroll
                for (int ww = 0; ww < 8; ww++) s += red[ww * 512 + p * 32 + b];
                const float* X = gate ? Xz : Xr;
                float pre = X[((size_t)step * Hh + jg) * 32 + b] + s;
                const float* ctx = gate ? ctxZ : ctxR;
                if (ctx) pre += ctx[jg * 32 + b];
                float sg = 1.f / (1.f + __expf(-pre));
                if (gate == 0) {
                    int hi = ptidx(jg, b);
                    rhT2[hi] = sg * hT2[hi];
                } else {
                    zs[col * 32 + b] = sg;
                }
            }
        }
        gbar(tgt);
        // ---------- phase B: candidate + blend ----------
        {
            unsigned long long acc[8];
#pragma unroll
            for (int p = 0; p < 8; p++) acc[p] = 0ull;
            float2 h0 = *(const float2*)(rhT2 + (off) * 64 + 2 * lane);
            float2 h1 = *(const float2*)(rhT2 + (off + 1) * 64 + 2 * lane);
            for (int i = 0; i < len; i += 2) {
                float2 n0, n1;
                if (i + 2 < len) {
                    n0 = *(const float2*)(rhT2 + (off + i + 2) * 64 + 2 * lane);
                    n1 = *(const float2*)(rhT2 + (off + i + 3) * 64 + 2 * lane);
                }
                int k0 = (off + i) * 2;
                unsigned long long h0p = pack2(h0), h1p = pack2(h1);
#pragma unroll
                for (int p = 0; p < 8; p++) {
                    float4 u = *(const float4*)(usc + p * 1000 + k0);
                    ffma2(acc[p], h0p, pack2f(u.x, u.y));
                    ffma2(acc[p], h1p, pack2f(u.z, u.w));
                }
                h0 = n0; h1 = n1;
            }
            __syncthreads();
#pragma unroll
            for (int p = 0; p < 8; p++) {
                float2 a = unpack2(acc[p]);
                red[w * 256 + p * 32 + lane] = a.x + a.y;
            }
            __syncthreads();
            {
                int col = tid >> 5, b = tid & 31;
                int jg = jbase + col;
                float s = 0.f;
#pragma unroll
                for (int ww = 0; ww < 8; ww++) s += red[ww * 256 + col * 32 + b];
                float pre = Xc[((size_t)step * Hh + jg) * 32 + b] + s;
                if (ctxC) pre += ctxC[jg * 32 + b];
                float cand = tanhf(pre);
                float zv = zs[col * 32 + b];
                int hi = ptidx(jg, b);
                float hv = hT2[hi];
                float hn = (1.f - zv) * hv + zv * cand;
                hT2[hi] = hn;
                if (Sst != nullptr && step + 1 < nsteps)
                    Sst[((size_t)(step + 1) * 32 + b) * Hh + jg] = hn;
            }
        }
        gbar(tgt);
    }
}

// ---------------- host orchestration ----------------
extern "C" void kernel_launch(void* const* d_in, const int* in_sizes, int n_in,
                              void* d_out, int out_size)
{
    const int*   src     = (const int*)d_in[0];
    const int*   tgt     = (const int*)d_in[1];
    const float* src_emb = (const float*)d_in[3];
    const float* tgt_emb = (const float*)d_in[4];
    const float* enc_W   = (const float*)d_in[5];
    const float* enc_Wz  = (const float*)d_in[6];
    const float* enc_Wr  = (const float*)d_in[7];
    const float* enc_U   = (const float*)d_in[8];
    const float* enc_Uz  = (const float*)d_in[9];
    const float* enc_Ur  = (const float*)d_in[10];
    const float* enc_b   = (const float*)d_in[11];
    const float* enc_bz  = (const float*)d_in[12];
    const float* enc_br  = (const float*)d_in[13];
    const float* dec_W   = (const float*)d_in[14];
    const float* dec_Wz  = (const float*)d_in[15];
    const float* dec_Wr  = (const float*)d_in[16];
    const float* dec_U   = (const float*)d_in[17];
    const float* dec_Uz  = (const float*)d_in[18];
    const float* dec_Ur  = (const float*)d_in[19];
    const float* dec_C   = (const float*)d_in[20];
    const float* dec_Cz  = (const float*)d_in[21];
    const float* dec_Cr  = (const float*)d_in[22];
    const float* dec_b   = (const float*)d_in[23];
    const float* dec_bz  = (const float*)d_in[24];
    const float* dec_br  = (const float*)d_in[25];
    const float* W_s     = (const float*)d_in[26];
    const float* U_o     = (const float*)d_in[27];
    const float* V_o     = (const float*)d_in[28];
    const float* C_o     = (const float*)d_in[29];
    const float* W_o     = (const float*)d_in[30];
    float* out = (float*)d_out;

    float *Xr, *Xz, *Xc, *Yr, *Yz, *Yc, *Yo;
    float *hT2, *s0T, *rhT2, *cCrT, *cCzT, *cCT, *cCo, *Sst, *tfull, *tmax;
    unsigned* barctr;
    cudaGetSymbolAddress((void**)&Xr, g_Xr);
    cudaGetSymbolAddress((void**)&Xz, g_Xz);
    cudaGetSymbolAddress((void**)&Xc, g_Xc);
    cudaGetSymbolAddress((void**)&Yr, g_Yr);
    cudaGetSymbolAddress((void**)&Yz, g_Yz);
    cudaGetSymbolAddress((void**)&Yc, g_Yc);
    cudaGetSymbolAddress((void**)&Yo, g_Yo);
    cudaGetSymbolAddress((void**)&hT2, g_hT2);
    cudaGetSymbolAddress((void**)&s0T, g_s0T);
    cudaGetSymbolAddress((void**)&rhT2, g_rhT2);
    cudaGetSymbolAddress((void**)&cCrT, g_cCrT);
    cudaGetSymbolAddress((void**)&cCzT, g_cCzT);
    cudaGetSymbolAddress((void**)&cCT,  g_cCT);
    cudaGetSymbolAddress((void**)&cCo, g_cCo);
    cudaGetSymbolAddress((void**)&Sst, g_S);
    cudaGetSymbolAddress((void**)&tfull, g_tfull);
    cudaGetSymbolAddress((void**)&tmax, g_tmax);
    cudaGetSymbolAddress((void**)&barctr, g_barctr);

    __half *eWr2, *eWz2, *eW2, *dWr2, *dWz2, *dW2, *Vo2;
    __half *Ws2, *Cr2, *Cz2, *C2, *Co2, *Uo2, *Wo2;
    __half *X2, *Y2, *cT2, *S2, *T2;
    cudaGetSymbolAddress((void**)&eWr2, g2_eWr);
    cudaGetSymbolAddress((void**)&eWz2, g2_eWz);
    cudaGetSymbolAddress((void**)&eW2,  g2_eW);
    cudaGetSymbolAddress((void**)&dWr2, g2_dWr);
    cudaGetSymbolAddress((void**)&dWz2, g2_dWz);
    cudaGetSymbolAddress((void**)&dW2,  g2_dW);
    cudaGetSymbolAddress((void**)&Vo2,  g2_Vo);
    cudaGetSymbolAddress((void**)&Ws2,  g2_Ws);
    cudaGetSymbolAddress((void**)&Cr2,  g2_Cr);
    cudaGetSymbolAddress((void**)&Cz2,  g2_Cz);
    cudaGetSymbolAddress((void**)&C2,   g2_C);
    cudaGetSymbolAddress((void**)&Co2,  g2_Co);
    cudaGetSymbolAddress((void**)&Uo2,  g2_Uo);
    cudaGetSymbolAddress((void**)&Wo2,  g2_Wo);
    cudaGetSymbolAddress((void**)&X2,   g2_X);
    cudaGetSymbolAddress((void**)&Y2,   g2_Y);
    cudaGetSymbolAddress((void**)&cT2,  g2_cT);
    cudaGetSymbolAddress((void**)&S2,   g2_S);
    cudaGetSymbolAddress((void**)&T2,   g2_T);

    cudaFuncSetAttribute(recur_persist, cudaFuncAttributeMaxDynamicSharedMemorySize, SMEM_RECUR);
    cudaFuncSetAttribute(bf16_gemm, cudaFuncAttributeMaxDynamicSharedMemorySize, GSMEM_BYTES);

    // ---- weight converts ----
    {
        ConvBatch cb = {};
        const float* s[7] = {enc_Wr, enc_Wz, enc_W, dec_Wr, dec_Wz, dec_W, V_o};
        __half* d[7] = {eWr2, eWz2, eW2, dWr2, dWz2, dW2, Vo2};
        for (int i = 0; i < 7; i++) cb.e[i] = {s[i], d[i], Hh, Ee, K2E, 1, 0};
        int total = Hh * (K2E / 8);
        dim3 gr((total + 255) / 256, 7);
        conv_k<<<gr, 256>>>(cb);
    }
    {
        ConvBatch cb = {};
        const float* s[6] = {W_s, dec_Cr, dec_Cz, dec_C, C_o, U_o};
        __half* d[6] = {Ws2, Cr2, Cz2, C2, Co2, Uo2};
        for (int i = 0; i < 6; i++) cb.e[i] = {s[i], d[i], Hh, Hh, K2H, 1, 0};
        int total = Hh * (K2H / 8);
        dim3 gr((total + 255) / 256, 6);
        conv_k<<<gr, 256>>>(cb);
    }
    {
        ConvBatch cb = {};
        cb.e[0] = {W_o, Wo2, Vv, Mm, K2M, 1, 0};
        int total = Vv * (K2M / 8);
        dim3 gr((total + 255) / 256, 1);
        conv_k<<<gr, 256>>>(cb);
    }

    // ---- fused gathers ----
    gather_trip<<<RS, 128>>>(src, src_emb, X2, Ss);
    gather_trip<<<RT, 128>>>(tgt, tgt_emb, Y2, Tt);

    // ---- input projections ----
    {
        MultiGemm g = {};
        g.A2 = X2; g.M = RS; g.N = Hh; g.K2p = K2E; g.ldc = Hh;
        g.B2[0] = eWr2; g.C[0] = Xr; g.bias[0] = enc_br; g.mode[0] = 4;
        g.B2[1] = eWz2; g.C[1] = Xz; g.bias[1] = enc_bz; g.mode[1] = 4;
        g.B2[2] = eW2;  g.C[2] = Xc; g.bias[2] = enc_b;  g.mode[2] = 4;
        dim3 gr((Hh + GBN - 1) / GBN, (RS + GBM - 1) / GBM, 3);
        bf16_gemm<<<gr, 256, GSMEM_BYTES>>>(g);
    }
    {
        MultiGemm g = {};
        g.A2 = Y2; g.M = RT; g.N = Hh; g.K2p = K2E; g.ldc = Hh;
        g.B2[0] = dWr2; g.C[0] = Yr; g.bias[0] = dec_br; g.mode[0] = 4;
        g.B2[1] = dWz2; g.C[1] = Yz; g.bias[1] = dec_bz; g.mode[1] = 4;
        g.B2[2] = dW2;  g.C[2] = Yc; g.bias[2] = dec_b;  g.mode[2] = 4;
        g.B2[3] = Vo2;  g.C[3] = Yo; g.bias[3] = nullptr; g.mode[3] = 0;
        dim3 gr((Hh + GBN - 1) / GBN, (RT + GBM - 1) / GBM, 4);
        bf16_gemm<<<gr, 256, GSMEM_BYTES>>>(g);
    }

    // ---- encoder recurrence ----
    cudaMemsetAsync(hT2, 0, (size_t)Hh * Bb * sizeof(float));
    cudaMemsetAsync(barctr, 0, sizeof(unsigned));
    recur_persist<<<NBLK, 256, SMEM_RECUR>>>(hT2, rhT2,
        enc_Ur, enc_Uz, enc_U, Xr, Xz, Xc,
        nullptr, nullptr, nullptr, nullptr, Ss);

    // ---- context projections ----
    {
        ConvBatch cb = {};
        cb.e[0] = {hT2, cT2, Bb, Hh, K2H, 0, 1};
        int total = Bb * (K2H / 8);
        dim3 gr((total + 255) / 256, 1);
        conv_k<<<gr, 256>>>(cb);
    }
    {
        MultiGemm g = {};
        g.A2 = cT2; g.M = Bb; g.N = Hh; g.K2p = K2H; g.ldc = Hh;
        g.B2[0] = Ws2; g.C[0] = Sst;  g.add1[0] = s0T; g.mode[0] = 5;
        g.B2[1] = Cr2; g.C[1] = cCrT; g.mode[1] = 4;
        g.B2[2] = Cz2; g.C[2] = cCzT; g.mode[2] = 4;
        g.B2[3] = C2;  g.C[3] = cCT;  g.mode[3] = 4;
        g.B2[4] = Co2; g.C[4] = cCo;  g.mode[4] = 0;
        dim3 gr((Hh + GBN - 1) / GBN, 1, 5);
        bf16_gemm<<<gr, 256, GSMEM_BYTES>>>(g);
    }

    // ---- decoder recurrence ----
    cudaMemsetAsync(barctr, 0, sizeof(unsigned));
    recur_persist<<<NBLK, 256, SMEM_RECUR>>>(s0T, rhT2,
        dec_Ur, dec_Uz, dec_U, Yr, Yz, Yc,
        cCrT, cCzT, cCT, Sst, Tt);

    // ---- output layer ----
    {
        ConvBatch cb = {};
        cb.e[0] = {Sst, S2, RT, Hh, K2H, 0, 0};
        int total = RT * (K2H / 8);
        dim3 gr((total + 255) / 256, 1);
        conv_k<<<gr, 256>>>(cb);
    }
    {
        MultiGemm g = {};
        g.A2 = S2; g.M = RT; g.N = Hh; g.K2p = K2H; g.ldc = Hh;
        g.B2[0] = Uo2; g.C[0] = tfull; g.add1[0] = Yo; g.add2[0] = cCo; g.mode[0] = 2;
        dim3 gr((Hh + GBN - 1) / GBN, (RT + GBM - 1) / GBM, 1);
        bf16_gemm<<<gr, 256, GSMEM_BYTES>>>(g);
    }
    maxout_k<<<(RT * Mm + 255) / 256, 256>>>(tfull, tmax);
    {
        ConvBatch cb = {};
        cb.e[0] = {tmax, T2, RT, Mm, K2M, 0, 0};
        int total = RT * (K2M / 8);
        dim3 gr((total + 255) / 256, 1);
        conv_k<<<gr, 256>>>(cb);
    }
    {
        MultiGemm g = {};
        g.A2 = T2; g.M = RT; g.N = Vv; g.K2p = K2M; g.ldc = Vv;
        g.B2[0] = Wo2; g.C[0] = out; g.mode[0] = 3;
        dim3 gr((Vv + GBN - 1) / GBN, (RT + GBM - 1) / GBM, 1);
        bf16_gemm<<<gr, 256, GSMEM_BYTES>>>(g);
    }
}

// round 14
// speedup vs baseline: 1.9896x; 1.1759x over previous
#include <cuda_runtime.h>
#include <cuda_fp16.h>
#include <math.h>
#include <stdint.h>

#define Bb 32
#define Ss 24
#define Tt 24
#define Vv 30000
#define Ee 620
#define Hh 1000
#define Mm 500
#define RS (Ss*Bb)   /* 768 */
#define RT (Tt*Bb)   /* 768 */
#define NBLK 125
#define NCOLS 8

#define K2E 1280
#define K2H 2048
#define K2M 1024

// ---------------- fp32 scratch ----------------
__device__ float g_Xr[RS*Hh];
__device__ float g_Xz[RS*Hh];
__device__ float g_Xc[RS*Hh];
__device__ float g_Yr[RT*Hh];
__device__ float g_Yz[RT*Hh];
__device__ float g_Yc[RT*Hh];
__device__ float g_Yo[RT*Hh];
__device__ float g_hT2[Hh*Bb];
__device__ float g_s0T[Hh*Bb];
__device__ float g_rhT2[Hh*Bb];
__device__ float g_cCrT[Hh*Bb];
__device__ float g_cCzT[Hh*Bb];
__device__ float g_cCT [Hh*Bb];
__device__ float g_cCo[Bb*Hh];
__device__ float g_S[RT*Hh];
__device__ float g_tfull[RT*Hh];
__device__ float g_tmax[RT*Mm];
__device__ unsigned g_barctr;

// ---------------- fp16 doubled operands (A: [hi|lo], B: [hi|hi]) ----------------
__device__ __half g2_eWr[Hh*K2E];
__device__ __half g2_eWz[Hh*K2E];
__device__ __half g2_eW [Hh*K2E];
__device__ __half g2_dWr[Hh*K2E];
__device__ __half g2_dWz[Hh*K2E];
__device__ __half g2_dW [Hh*K2E];
__device__ __half g2_Vo [Hh*K2E];
__device__ __half g2_Ws [Hh*K2H];
__device__ __half g2_Cr [Hh*K2H];
__device__ __half g2_Cz [Hh*K2H];
__device__ __half g2_C  [Hh*K2H];
__device__ __half g2_Co [Hh*K2H];
__device__ __half g2_Uo [Hh*K2H];
__device__ __half g2_Wo [Vv*K2M];
__device__ __half g2_X  [RS*K2E];
__device__ __half g2_Y  [RT*K2E];
__device__ __half g2_cT [Bb*K2H];
__device__ __half g2_S  [RT*K2H];
__device__ __half g2_T  [RT*K2M];

__device__ __forceinline__ int ptidx(int j, int b) { return ((j >> 1) * 64) + 2 * b + (j & 1); }

// ---------------- embedding gather fused with fp16 doubling ----------------
__global__ void gather_trip(const int* __restrict__ tok, const float* __restrict__ emb,
                            __half* __restrict__ out2, int L)
{
    int r = blockIdx.x;
    int s = r >> 5, b = r & 31;
    int token = tok[b * L + s];
    const float* srcp = emb + (long)token * Ee;
    __half* dst = out2 + (size_t)r * K2E;
    for (int e = threadIdx.x; e < Ee; e += blockDim.x) {
        float v = srcp[e];
        __half h = __float2half(v);
        __half l = __float2half(v - __half2float(h));
        dst[e] = h; dst[Ee + e] = l;
    }
}

// ---------------- fp32 -> doubled fp16 convert ----------------
struct ConvEntry { const float* src; __half* dst; int R, K, K2p, typeB, paired; };
struct ConvBatch { ConvEntry e[8]; };

__global__ void conv_k(ConvBatch cb)
{
    ConvEntry E = cb.e[blockIdx.y];
    int per = E.K2p >> 3;
    int total = E.R * per;
    int i = blockIdx.x * 256 + threadIdx.x;
    if (i >= total) return;
    int r = i / per, c8 = (i - r * per) * 8;
    const float* s = E.src + (size_t)r * E.K;
    __half o[8];
#pragma unroll
    for (int j = 0; j < 8; j++) {
        int k2 = c8 + j;
        int K = E.K;
        float v = 0.f; int wantLo = 0;
        int k = -1;
        if (k2 < K)          { k = k2;     wantLo = 0; }
        else if (k2 < 2 * K) { k = k2 - K; wantLo = E.typeB ? 0 : 1; }
        if (k >= 0) v = E.paired ? E.src[((k >> 1) << 6) + 2 * r + (k & 1)] : s[k];
        __half h = __float2half(v);
        o[j] = wantLo ? __float2half(v - __half2float(h)) : h;
    }
    *(float4*)(E.dst + (size_t)r * E.K2p + c8) = *(float4*)o;
}

// ================= fp16 GEMM (cp.async double-buffered) =================
struct MultiGemm {
    const __half* A2;
    const __half* B2[5];
    float*       C[5];
    const float* bias[5];
    const float* add1[5];
    const float* add2[5];
    int mode[5];
    int M, N, K2p, ldc;
};

#define GBM 128
#define GBN 128
#define GBK 64
#define GSK 72
#define GSTAGE_ELEMS (128*GSK)
#define GSMEM_BYTES (4*GSTAGE_ELEMS*2)

__device__ __forceinline__ uint32_t smem_u32(const void* p) {
    return (uint32_t)__cvta_generic_to_shared(p);
}
__device__ __forceinline__ void ldsm4(uint32_t &r0, uint32_t &r1, uint32_t &r2, uint32_t &r3, uint32_t a) {
    asm volatile("ldmatrix.sync.aligned.m8n8.x4.shared.b16 {%0,%1,%2,%3}, [%4];\n"
        : "=r"(r0), "=r"(r1), "=r"(r2), "=r"(r3) : "r"(a));
}
__device__ __forceinline__ void mma_f16(float* c, const uint32_t* a, uint32_t b0, uint32_t b1) {
    asm volatile("mma.sync.aligned.m16n8k16.row.col.f32.f16.f16.f32 "
        "{%0,%1,%2,%3},{%4,%5,%6,%7},{%8,%9},{%0,%1,%2,%3};\n"
        : "+f"(c[0]), "+f"(c[1]), "+f"(c[2]), "+f"(c[3])
        : "r"(a[0]), "r"(a[1]), "r"(a[2]), "r"(a[3]), "r"(b0), "r"(b1));
}
__device__ __forceinline__ void cpasync16(uint32_t daddr, const void* src, int sbytes) {
    asm volatile("cp.async.cg.shared.global [%0], [%1], 16, %2;\n"
        :: "r"(daddr), "l"(src), "r"(sbytes));
}

__global__ __launch_bounds__(256, 2)
void bf16_gemm(MultiGemm g)
{
    extern __shared__ __half smem[];
    __half* sA = smem;
    __half* sB = smem + 2 * GSTAGE_ELEMS;

    int z = blockIdx.z;
    const __half* A  = g.A2;
    const __half* Bm = g.B2[z];
    float* C          = g.C[z];
    const float* bias = g.bias[z];
    const float* add1 = g.add1[z];
    const float* add2 = g.add2[z];
    int mode = g.mode[z];
    int M = g.M, N = g.N, K2p = g.K2p, ldc = g.ldc;

    int t = threadIdx.x, lane = t & 31, wid = t >> 5;
    int wm = wid & 1, wn = wid >> 1;
    int m0 = blockIdx.y * GBM, n0 = blockIdx.x * GBN;

    float acc[4][4][4];
#pragma unroll
    for (int i = 0; i < 4; i++)
#pragma unroll
        for (int j = 0; j < 4; j++)
#pragma unroll
            for (int c = 0; c < 4; c++) acc[i][j][c] = 0.f;

    int sel = lane >> 3, l7 = lane & 7;
    int ar = (sel & 1) * 8 + l7;
    int ac = (sel >> 1) * 8;
    int br = (sel >> 1) * 8 + l7;
    int bc = (sel & 1) * 8;

    int KT = K2p / GBK;

    auto loadStage = [&](int kt, int st) {
        int kbase = kt * GBK;
#pragma unroll
        for (int i = 0; i < 4; i++) {
            int idx = t + i * 256;
            int row = idx >> 3, sg = idx & 7;
            {
                int gr = m0 + row;
                int ok = (gr < M);
                const __half* src = A + (size_t)(ok ? gr : 0) * K2p + kbase + sg * 8;
                cpasync16(smem_u32(&sA[st * GSTAGE_ELEMS + row * GSK + sg * 8]), src, ok ? 16 : 0);
            }
            {
                int gr = n0 + row;
                int ok = (gr < N);
                const __half* src = Bm + (size_t)(ok ? gr : 0) * K2p + kbase + sg * 8;
                cpasync16(smem_u32(&sB[st * GSTAGE_ELEMS + row * GSK + sg * 8]), src, ok ? 16 : 0);
            }
        }
        asm volatile("cp.async.commit_group;\n");
    };

    loadStage(0, 0);

    for (int kt = 0; kt < KT; kt++) {
        int st = kt & 1;
        if (kt + 1 < KT) {
            loadStage(kt + 1, st ^ 1);
            asm volatile("cp.async.wait_group 1;\n");
        } else {
            asm volatile("cp.async.wait_group 0;\n");
        }
        __syncthreads();

        const __half* a_st = sA + st * GSTAGE_ELEMS;
        const __half* b_st = sB + st * GSTAGE_ELEMS;
#pragma unroll
        for (int kh = 0; kh < 4; kh++) {
            uint32_t af[4][4], bf[4][2];
#pragma unroll
            for (int mi = 0; mi < 4; mi++) {
                uint32_t addr = smem_u32(&a_st[(wm * 64 + mi * 16 + ar) * GSK + kh * 16 + ac]);
                ldsm4(af[mi][0], af[mi][1], af[mi][2], af[mi][3], addr);
            }
#pragma unroll
            for (int p = 0; p < 2; p++) {
                uint32_t r0, r1, r2, r3;
                uint32_t addr = smem_u32(&b_st[(wn * 32 + p * 16 + br) * GSK + kh * 16 + bc]);
                ldsm4(r0, r1, r2, r3, addr);
                bf[2*p][0] = r0; bf[2*p][1] = r1; bf[2*p+1][0] = r2; bf[2*p+1][1] = r3;
            }
#pragma unroll
            for (int mi = 0; mi < 4; mi++)
#pragma unroll
                for (int ni = 0; ni < 4; ni++)
                    mma_f16(acc[mi][ni], af[mi], bf[ni][0], bf[ni][1]);
        }
        __syncthreads();
    }

    int gq = lane >> 2, tig = lane & 3;
#pragma unroll
    for (int mi = 0; mi < 4; mi++) {
#pragma unroll
        for (int ni = 0; ni < 4; ni++) {
#pragma unroll
            for (int c = 0; c < 4; c++) {
                int row = m0 + wm * 64 + mi * 16 + gq + ((c >> 1) ? 8 : 0);
                int col = n0 + wn * 32 + ni * 8 + tig * 2 + (c & 1);
                if (row >= M || col >= N) continue;
                float v = acc[mi][ni][c];
                if (mode == 0) {
                    if (bias) v += bias[col];
                    C[(size_t)row * ldc + col] = v;
                } else if (mode == 2) {
                    v += add1[(size_t)row * ldc + col] + add2[(size_t)(row & 31) * ldc + col];
                    C[(size_t)row * ldc + col] = v;
                } else if (mode == 3) {
                    int b = row & 31, ti = row >> 5;
                    C[(size_t)b * (Tt * Vv) + (size_t)ti * Vv + col] = v;
                } else if (mode == 4) {
                    if (bias) v += bias[col];
                    int b = row & 31, ti = row >> 5;
                    C[((size_t)ti * Hh + col) * 32 + b] = v;
                } else { // 5
                    int b = row & 31;
                    float tv = tanhf(v);
                    C[(size_t)b * Hh + col] = tv;
                    ((float*)add1)[ptidx(col, b)] = tv;
                }
            }
        }
    }
}

// ---------------- maxout ----------------
__global__ void maxout_k(const float* __restrict__ tf, float* __restrict__ tm)
{
    int i = blockIdx.x * blockDim.x + threadIdx.x;
    int total = RT * Mm;
    if (i < total) {
        int r = i / Mm, m = i - r * Mm;
        tm[i] = fmaxf(tf[r * Hh + 2 * m], tf[r * Hh + 2 * m + 1]);
    }
}

// ================= persistent recurrence =================
__device__ __forceinline__ unsigned long long pack2(float2 v) {
    unsigned long long r;
    asm("mov.b64 %0, {%1, %2};" : "=l"(r) : "f"(v.x), "f"(v.y));
    return r;
}
__device__ __forceinline__ unsigned long long pack2f(float a, float b) {
    unsigned long long r;
    asm("mov.b64 %0, {%1, %2};" : "=l"(r) : "f"(a), "f"(b));
    return r;
}
__device__ __forceinline__ float2 unpack2(unsigned long long v) {
    float2 r;
    asm("mov.b64 {%0, %1}, %2;" : "=f"(r.x), "=f"(r.y) : "l"(v));
    return r;
}
__device__ __forceinline__ void ffma2(unsigned long long &acc, unsigned long long a, unsigned long long b) {
    asm("fma.rn.f32x2 %0, %1, %2, %0;" : "+l"(acc) : "l"(a), "l"(b));
}

__device__ __forceinline__ void gbar(unsigned &tgt) {
    __threadfence();
    __syncthreads();
    if (threadIdx.x == 0) {
        atomicAdd(&g_barctr, 1u);
        unsigned v;
        do {
            asm volatile("ld.acquire.gpu.global.u32 %0, [%1];" : "=r"(v) : "l"(&g_barctr) : "memory");
            if (v >= tgt) break;
            __nanosleep(16);
        } while (true);
    }
    __syncthreads();
    tgt += gridDim.x;
}

#define SMEM_RECUR (28352*4)

__global__ __launch_bounds__(256, 1)
void recur_persist(float* __restrict__ hT2, float* __restrict__ rhT2,
    const float* __restrict__ GUr, const float* __restrict__ GUz, const float* __restrict__ GUc,
    const float* __restrict__ Xr, const float* __restrict__ Xz, const float* __restrict__ Xc,
    const float* __restrict__ ctxR, const float* __restrict__ ctxZ, const float* __restrict__ ctxC,
    float* __restrict__ Sst, int nsteps)
{
    extern __shared__ float sm[];
    float* usr = sm;
    float* usz = sm + 8000;
    float* usc = sm + 16000;
    float* red = sm + 24000;
    float* zs  = sm + 28096;
    int tid = threadIdx.x, lane = tid & 31, w = tid >> 5;
    int jbase = blockIdx.x * NCOLS;

    for (int i4 = tid; i4 < 2000; i4 += 256) {
        int row = i4 / 250, k4 = (i4 % 250) * 4;
        *(float4*)(usr + row * 1000 + k4) = *(const float4*)(GUr + (size_t)(jbase + row) * 1000 + k4);
        *(float4*)(usz + row * 1000 + k4) = *(const float4*)(GUz + (size_t)(jbase + row) * 1000 + k4);
        *(float4*)(usc + row * 1000 + k4) = *(const float4*)(GUc + (size_t)(jbase + row) * 1000 + k4);
    }
    __syncthreads();

    // per-warp kk2 slices, all lens multiple of 4 (chunk-4 triple buffering)
    const int offs[8] = {0, 64, 128, 192, 256, 320, 380, 440};
    const int lens[8] = {64, 64, 64, 64, 64, 60, 60, 60};
    int off = offs[w];
    int nch = lens[w] >> 2;
    unsigned tgt = gridDim.x;

    for (int step = 0; step < nsteps; step++) {
        // ---------- phase A: r,z gates ----------
        {
            unsigned long long acc[16];
#pragma unroll
            for (int p = 0; p < 16; p++) acc[p] = 0ull;
            float2 b0[4], b1[4], b2[4];
#pragma unroll
            for (int q = 0; q < 4; q++) b0[q] = *(const float2*)(hT2 + (off + q) * 64 + 2 * lane);
#pragma unroll
            for (int q = 0; q < 4; q++) b1[q] = *(const float2*)(hT2 + (off + 4 + q) * 64 + 2 * lane);
            for (int ch = 0; ch < nch; ch++) {
                if (ch + 2 < nch) {
#pragma unroll
                    for (int q = 0; q < 4; q++)
                        b2[q] = *(const float2*)(hT2 + (off + (ch + 2) * 4 + q) * 64 + 2 * lane);
                }
#pragma unroll
                for (int q2 = 0; q2 < 4; q2 += 2) {
                    int k0 = (off + ch * 4 + q2) * 2;
                    unsigned long long h0p = pack2(b0[q2]), h1p = pack2(b0[q2 + 1]);
#pragma unroll
                    for (int p = 0; p < 16; p++) {
                        const float* us = (p & 1) ? usz : usr;
                        float4 u = *(const float4*)(us + (p >> 1) * 1000 + k0);
                        ffma2(acc[p], h0p, pack2f(u.x, u.y));
                        ffma2(acc[p], h1p, pack2f(u.z, u.w));
                    }
                }
#pragma unroll
                for (int q = 0; q < 4; q++) { b0[q] = b1[q]; b1[q] = b2[q]; }
            }
#pragma unroll
            for (int p = 0; p < 16; p++) {
                float2 a = unpack2(acc[p]);
                red[w * 512 + p * 32 + lane] = a.x + a.y;
            }
            __syncthreads();
            for (int o = tid; o < 512; o += 256) {
                int p = o >> 5, b = o & 31;
                int col = p >> 1, gate = p & 1;
                int jg = jbase + col;
                float s = 0.f;
#pragma unroll
                for (int ww = 0; ww < 8; ww++) s += red[ww * 512 + p * 32 + b];
                const float* X = gate ? Xz : Xr;
                float pre = X[((size_t)step * Hh + jg) * 32 + b] + s;
                const float* ctx = gate ? ctxZ : ctxR;
                if (ctx) pre += ctx[jg * 32 + b];
                float sg = 1.f / (1.f + __expf(-pre));
                if (gate == 0) {
                    int hi = ptidx(jg, b);
                    rhT2[hi] = sg * hT2[hi];
                } else {
                    zs[col * 32 + b] = sg;
                }
            }
        }
        gbar(tgt);
        // ---------- phase B: candidate + blend ----------
        {
            unsigned long long acc[8];
#pragma unroll
            for (int p = 0; p < 8; p++) acc[p] = 0ull;
            float2 b0[4], b1[4], b2[4];
#pragma unroll
            for (int q = 0; q < 4; q++) b0[q] = *(const float2*)(rhT2 + (off + q) * 64 + 2 * lane);
#pragma unroll
            for (int q = 0; q < 4; q++) b1[q] = *(const float2*)(rhT2 + (off + 4 + q) * 64 + 2 * lane);
            for (int ch = 0; ch < nch; ch++) {
                if (ch + 2 < nch) {
#pragma unroll
                    for (int q = 0; q < 4; q++)
                        b2[q] = *(const float2*)(rhT2 + (off + (ch + 2) * 4 + q) * 64 + 2 * lane);
                }
#pragma unroll
                for (int q2 = 0; q2 < 4; q2 += 2) {
                    int k0 = (off + ch * 4 + q2) * 2;
                    unsigned long long h0p = pack2(b0[q2]), h1p = pack2(b0[q2 + 1]);
#pragma unroll
                    for (int p = 0; p < 8; p++) {
                        float4 u = *(const float4*)(usc + p * 1000 + k0);
                        ffma2(acc[p], h0p, pack2f(u.x, u.y));
                        ffma2(acc[p], h1p, pack2f(u.z, u.w));
                    }
                }
#pragma unroll
                for (int q = 0; q < 4; q++) { b0[q] = b1[q]; b1[q] = b2[q]; }
            }
            __syncthreads();
#pragma unroll
            for (int p = 0; p < 8; p++) {
                float2 a = unpack2(acc[p]);
                red[w * 256 + p * 32 + lane] = a.x + a.y;
            }
            __syncthreads();
            {
                int col = tid >> 5, b = tid & 31;
                int jg = jbase + col;
                float s = 0.f;
#pragma unroll
                for (int ww = 0; ww < 8; ww++) s += red[ww * 256 + col * 32 + b];
                float pre = Xc[((size_t)step * Hh + jg) * 32 + b] + s;
                if (ctxC) pre += ctxC[jg * 32 + b];
                float cand = tanhf(pre);
                float zv = zs[col * 32 + b];
                int hi = ptidx(jg, b);
                float hv = hT2[hi];
                float hn = (1.f - zv) * hv + zv * cand;
                hT2[hi] = hn;
                if (Sst != nullptr && step + 1 < nsteps)
                    Sst[((size_t)(step + 1) * 32 + b) * Hh + jg] = hn;
            }
        }
        gbar(tgt);
    }
}

// ---------------- host orchestration ----------------
extern "C" void kernel_launch(void* const* d_in, const int* in_sizes, int n_in,
                              void* d_out, int out_size)
{
    const int*   src     = (const int*)d_in[0];
    const int*   tgt     = (const int*)d_in[1];
    const float* src_emb = (const float*)d_in[3];
    const float* tgt_emb = (const float*)d_in[4];
    const float* enc_W   = (const float*)d_in[5];
    const float* enc_Wz  = (const float*)d_in[6];
    const float* enc_Wr  = (const float*)d_in[7];
    const float* enc_U   = (const float*)d_in[8];
    const float* enc_Uz  = (const float*)d_in[9];
    const float* enc_Ur  = (const float*)d_in[10];
    const float* enc_b   = (const float*)d_in[11];
    const float* enc_bz  = (const float*)d_in[12];
    const float* enc_br  = (const float*)d_in[13];
    const float* dec_W   = (const float*)d_in[14];
    const float* dec_Wz  = (const float*)d_in[15];
    const float* dec_Wr  = (const float*)d_in[16];
    const float* dec_U   = (const float*)d_in[17];
    const float* dec_Uz  = (const float*)d_in[18];
    const float* dec_Ur  = (const float*)d_in[19];
    const float* dec_C   = (const float*)d_in[20];
    const float* dec_Cz  = (const float*)d_in[21];
    const float* dec_Cr  = (const float*)d_in[22];
    const float* dec_b   = (const float*)d_in[23];
    const float* dec_bz  = (const float*)d_in[24];
    const float* dec_br  = (const float*)d_in[25];
    const float* W_s     = (const float*)d_in[26];
    const float* U_o     = (const float*)d_in[27];
    const float* V_o     = (const float*)d_in[28];
    const float* C_o     = (const float*)d_in[29];
    const float* W_o     = (const float*)d_in[30];
    float* out = (float*)d_out;

    float *Xr, *Xz, *Xc, *Yr, *Yz, *Yc, *Yo;
    float *hT2, *s0T, *rhT2, *cCrT, *cCzT, *cCT, *cCo, *Sst, *tfull, *tmax;
    unsigned* barctr;
    cudaGetSymbolAddress((void**)&Xr, g_Xr);
    cudaGetSymbolAddress((void**)&Xz, g_Xz);
    cudaGetSymbolAddress((void**)&Xc, g_Xc);
    cudaGetSymbolAddress((void**)&Yr, g_Yr);
    cudaGetSymbolAddress((void**)&Yz, g_Yz);
    cudaGetSymbolAddress((void**)&Yc, g_Yc);
    cudaGetSymbolAddress((void**)&Yo, g_Yo);
    cudaGetSymbolAddress((void**)&hT2, g_hT2);
    cudaGetSymbolAddress((void**)&s0T, g_s0T);
    cudaGetSymbolAddress((void**)&rhT2, g_rhT2);
    cudaGetSymbolAddress((void**)&cCrT, g_cCrT);
    cudaGetSymbolAddress((void**)&cCzT, g_cCzT);
    cudaGetSymbolAddress((void**)&cCT,  g_cCT);
    cudaGetSymbolAddress((void**)&cCo, g_cCo);
    cudaGetSymbolAddress((void**)&Sst, g_S);
    cudaGetSymbolAddress((void**)&tfull, g_tfull);
    cudaGetSymbolAddress((void**)&tmax, g_tmax);
    cudaGetSymbolAddress((void**)&barctr, g_barctr);

    __half *eWr2, *eWz2, *eW2, *dWr2, *dWz2, *dW2, *Vo2;
    __half *Ws2, *Cr2, *Cz2, *C2, *Co2, *Uo2, *Wo2;
    __half *X2, *Y2, *cT2, *S2, *T2;
    cudaGetSymbolAddress((void**)&eWr2, g2_eWr);
    cudaGetSymbolAddress((void**)&eWz2, g2_eWz);
    cudaGetSymbolAddress((void**)&eW2,  g2_eW);
    cudaGetSymbolAddress((void**)&dWr2, g2_dWr);
    cudaGetSymbolAddress((void**)&dWz2, g2_dWz);
    cudaGetSymbolAddress((void**)&dW2,  g2_dW);
    cudaGetSymbolAddress((void**)&Vo2,  g2_Vo);
    cudaGetSymbolAddress((void**)&Ws2,  g2_Ws);
    cudaGetSymbolAddress((void**)&Cr2,  g2_Cr);
    cudaGetSymbolAddress((void**)&Cz2,  g2_Cz);
    cudaGetSymbolAddress((void**)&C2,   g2_C);
    cudaGetSymbolAddress((void**)&Co2,  g2_Co);
    cudaGetSymbolAddress((void**)&Uo2,  g2_Uo);
    cudaGetSymbolAddress((void**)&Wo2,  g2_Wo);
    cudaGetSymbolAddress((void**)&X2,   g2_X);
    cudaGetSymbolAddress((void**)&Y2,   g2_Y);
    cudaGetSymbolAddress((void**)&cT2,  g2_cT);
    cudaGetSymbolAddress((void**)&S2,   g2_S);
    cudaGetSymbolAddress((void**)&T2,   g2_T);

    cudaFuncSetAttribute(recur_persist, cudaFuncAttributeMaxDynamicSharedMemorySize, SMEM_RECUR);
    cudaFuncSetAttribute(bf16_gemm, cudaFuncAttributeMaxDynamicSharedMemorySize, GSMEM_BYTES);

    // ---- weight converts ----
    {
        ConvBatch cb = {};
        const float* s[7] = {enc_Wr, enc_Wz, enc_W, dec_Wr, dec_Wz, dec_W, V_o};
        __half* d[7] = {eWr2, eWz2, eW2, dWr2, dWz2, dW2, Vo2};
        for (int i = 0; i < 7; i++) cb.e[i] = {s[i], d[i], Hh, Ee, K2E, 1, 0};
        int total = Hh * (K2E / 8);
        dim3 gr((total + 255) / 256, 7);
        conv_k<<<gr, 256>>>(cb);
    }
    {
        ConvBatch cb = {};
        const float* s[6] = {W_s, dec_Cr, dec_Cz, dec_C, C_o, U_o};
        __half* d[6] = {Ws2, Cr2, Cz2, C2, Co2, Uo2};
        for (int i = 0; i < 6; i++) cb.e[i] = {s[i], d[i], Hh, Hh, K2H, 1, 0};
        int total = Hh * (K2H / 8);
        dim3 gr((total + 255) / 256, 6);
        conv_k<<<gr, 256>>>(cb);
    }
    {
        ConvBatch cb = {};
        cb.e[0] = {W_o, Wo2, Vv, Mm, K2M, 1, 0};
        int total = Vv * (K2M / 8);
        dim3 gr((total + 255) / 256, 1);
        conv_k<<<gr, 256>>>(cb);
    }

    // ---- fused gathers ----
    gather_trip<<<RS, 128>>>(src, src_emb, X2, Ss);
    gather_trip<<<RT, 128>>>(tgt, tgt_emb, Y2, Tt);

    // ---- input projections ----
    {
        MultiGemm g = {};
        g.A2 = X2; g.M = RS; g.N = Hh; g.K2p = K2E; g.ldc = Hh;
        g.B2[0] = eWr2; g.C[0] = Xr; g.bias[0] = enc_br; g.mode[0] = 4;
        g.B2[1] = eWz2; g.C[1] = Xz; g.bias[1] = enc_bz; g.mode[1] = 4;
        g.B2[2] = eW2;  g.C[2] = Xc; g.bias[2] = enc_b;  g.mode[2] = 4;
        dim3 gr((Hh + GBN - 1) / GBN, (RS + GBM - 1) / GBM, 3);
        bf16_gemm<<<gr, 256, GSMEM_BYTES>>>(g);
    }
    {
        MultiGemm g = {};
        g.A2 = Y2; g.M = RT; g.N = Hh; g.K2p = K2E; g.ldc = Hh;
        g.B2[0] = dWr2; g.C[0] = Yr; g.bias[0] = dec_br; g.mode[0] = 4;
        g.B2[1] = dWz2; g.C[1] = Yz; g.bias[1] = dec_bz; g.mode[1] = 4;
        g.B2[2] = dW2;  g.C[2] = Yc; g.bias[2] = dec_b;  g.mode[2] = 4;
        g.B2[3] = Vo2;  g.C[3] = Yo; g.bias[3] = nullptr; g.mode[3] = 0;
        dim3 gr((Hh + GBN - 1) / GBN, (RT + GBM - 1) / GBM, 4);
        bf16_gemm<<<gr, 256, GSMEM_BYTES>>>(g);
    }

    // ---- encoder recurrence ----
    cudaMemsetAsync(hT2, 0, (size_t)Hh * Bb * sizeof(float));
    cudaMemsetAsync(barctr, 0, sizeof(unsigned));
    recur_persist<<<NBLK, 256, SMEM_RECUR>>>(hT2, rhT2,
        enc_Ur, enc_Uz, enc_U, Xr, Xz, Xc,
        nullptr, nullptr, nullptr, nullptr, Ss);

    // ---- context projections ----
    {
        ConvBatch cb = {};
        cb.e[0] = {hT2, cT2, Bb, Hh, K2H, 0, 1};
        int total = Bb * (K2H / 8);
        dim3 gr((total + 255) / 256, 1);
        conv_k<<<gr, 256>>>(cb);
    }
    {
        MultiGemm g = {};
        g.A2 = cT2; g.M = Bb; g.N = Hh; g.K2p = K2H; g.ldc = Hh;
        g.B2[0] = Ws2; g.C[0] = Sst;  g.add1[0] = s0T; g.mode[0] = 5;
        g.B2[1] = Cr2; g.C[1] = cCrT; g.mode[1] = 4;
        g.B2[2] = Cz2; g.C[2] = cCzT; g.mode[2] = 4;
        g.B2[3] = C2;  g.C[3] = cCT;  g.mode[3] = 4;
        g.B2[4] = Co2; g.C[4] = cCo;  g.mode[4] = 0;
        dim3 gr((Hh + GBN - 1) / GBN, 1, 5);
        bf16_gemm<<<gr, 256, GSMEM_BYTES>>>(g);
    }

    // ---- decoder recurrence ----
    cudaMemsetAsync(barctr, 0, sizeof(unsigned));
    recur_persist<<<NBLK, 256, SMEM_RECUR>>>(s0T, rhT2,
        dec_Ur, dec_Uz, dec_U, Yr, Yz, Yc,
        cCrT, cCzT, cCT, Sst, Tt);

    // ---- output layer ----
    {
        ConvBatch cb = {};
        cb.e[0] = {Sst, S2, RT, Hh, K2H, 0, 0};
        int total = RT * (K2H / 8);
        dim3 gr((total + 255) / 256, 1);
        conv_k<<<gr, 256>>>(cb);
    }
    {
        MultiGemm g = {};
        g.A2 = S2; g.M = RT; g.N = Hh; g.K2p = K2H; g.ldc = Hh;
        g.B2[0] = Uo2; g.C[0] = tfull; g.add1[0] = Yo; g.add2[0] = cCo; g.mode[0] = 2;
        dim3 gr((Hh + GBN - 1) / GBN, (RT + GBM - 1) / GBM, 1);
        bf16_gemm<<<gr, 256, GSMEM_BYTES>>>(g);
    }
    maxout_k<<<(RT * Mm + 255) / 256, 256>>>(tfull, tmax);
    {
        ConvBatch cb = {};
        cb.e[0] = {tmax, T2, RT, Mm, K2M, 0, 0};
        int total = RT * (K2M / 8);
        dim3 gr((total + 255) / 256, 1);
        conv_k<<<gr, 256>>>(cb);
    }
    {
        MultiGemm g = {};
        g.A2 = T2; g.M = RT; g.N = Vv; g.K2p = K2M; g.ldc = Vv;
        g.B2[0] = Wo2; g.C[0] = out; g.mode[0] = 3;
        dim3 gr((Vv + GBN - 1) / GBN, (RT + GBM - 1) / GBM, 1);
        bf16_gemm<<<gr, 256, GSMEM_BYTES>>>(g);
    }
}

// round 16
// speedup vs baseline: 2.0710x; 1.0409x over previous
#include <cuda_runtime.h>
#include <cuda_fp16.h>
#include <math.h>
#include <stdint.h>

#define Bb 32
#define Ss 24
#define Tt 24
#define Vv 30000
#define Ee 620
#define Hh 1000
#define Mm 500
#define RS (Ss*Bb)   /* 768 */
#define RT (Tt*Bb)   /* 768 */
#define NBLK 125
#define NCOLS 8

#define K2E 1280
#define K2H 2048
#define K2M 1024

// ---------------- fp32 scratch ----------------
__device__ float g_Xr[RS*Hh];
__device__ float g_Xz[RS*Hh];
__device__ float g_Xc[RS*Hh];
__device__ float g_Yr[RT*Hh];
__device__ float g_Yz[RT*Hh];
__device__ float g_Yc[RT*Hh];
__device__ float g_Yo[RT*Hh];
__device__ float g_hT2[Hh*Bb];
__device__ float g_s0T[Hh*Bb];
__device__ float g_rhT2[Hh*Bb];
__device__ float g_cCrT[Hh*Bb];
__device__ float g_cCzT[Hh*Bb];
__device__ float g_cCT [Hh*Bb];
__device__ float g_cCo[Bb*Hh];
__device__ float g_S[RT*Hh];
__device__ float g_tfull[RT*Hh];
__device__ float g_tmax[RT*Mm];
__device__ unsigned g_barctr;

// ---------------- fp16 doubled operands (A: [hi|lo], B: [hi|hi]) ----------------
__device__ __half g2_eWr[Hh*K2E];
__device__ __half g2_eWz[Hh*K2E];
__device__ __half g2_eW [Hh*K2E];
__device__ __half g2_dWr[Hh*K2E];
__device__ __half g2_dWz[Hh*K2E];
__device__ __half g2_dW [Hh*K2E];
__device__ __half g2_Vo [Hh*K2E];
__device__ __half g2_Ws [Hh*K2H];
__device__ __half g2_Cr [Hh*K2H];
__device__ __half g2_Cz [Hh*K2H];
__device__ __half g2_C  [Hh*K2H];
__device__ __half g2_Co [Hh*K2H];
__device__ __half g2_Uo [Hh*K2H];
__device__ __half g2_Wo [Vv*K2M];
__device__ __half g2_X  [RS*K2E];
__device__ __half g2_Y  [RT*K2E];
__device__ __half g2_cT [Bb*K2H];
__device__ __half g2_S  [RT*K2H];
__device__ __half g2_T  [RT*K2M];

__device__ __forceinline__ int ptidx(int j, int b) { return ((j >> 1) * 64) + 2 * b + (j & 1); }

// ---------------- embedding gather fused with fp16 doubling ----------------
__global__ void gather_trip(const int* __restrict__ tok, const float* __restrict__ emb,
                            __half* __restrict__ out2, int L)
{
    int r = blockIdx.x;
    int s = r >> 5, b = r & 31;
    int token = tok[b * L + s];
    const float* srcp = emb + (long)token * Ee;
    __half* dst = out2 + (size_t)r * K2E;
    for (int e = threadIdx.x; e < Ee; e += blockDim.x) {
        float v = srcp[e];
        __half h = __float2half(v);
        __half l = __float2half(v - __half2float(h));
        dst[e] = h; dst[Ee + e] = l;
    }
}

// ---------------- fp32 -> doubled fp16 convert ----------------
struct ConvEntry { const float* src; __half* dst; int R, K, K2p, typeB, paired; };
struct ConvBatch { ConvEntry e[8]; };

__global__ void conv_k(ConvBatch cb)
{
    ConvEntry E = cb.e[blockIdx.y];
    int per = E.K2p >> 3;
    int total = E.R * per;
    int i = blockIdx.x * 256 + threadIdx.x;
    if (i >= total) return;
    int r = i / per, c8 = (i - r * per) * 8;
    const float* s = E.src + (size_t)r * E.K;
    __half o[8];
#pragma unroll
    for (int j = 0; j < 8; j++) {
        int k2 = c8 + j;
        int K = E.K;
        float v = 0.f; int wantLo = 0;
        int k = -1;
        if (k2 < K)          { k = k2;     wantLo = 0; }
        else if (k2 < 2 * K) { k = k2 - K; wantLo = E.typeB ? 0 : 1; }
        if (k >= 0) v = E.paired ? E.src[((k >> 1) << 6) + 2 * r + (k & 1)] : s[k];
        __half h = __float2half(v);
        o[j] = wantLo ? __float2half(v - __half2float(h)) : h;
    }
    *(float4*)(E.dst + (size_t)r * E.K2p + c8) = *(float4*)o;
}

// ================= fp16 GEMM (cp.async double-buffered) =================
struct MultiGemm {
    const __half* A2;
    const __half* B2[5];
    float*       C[5];
    const float* bias[5];
    const float* add1[5];
    const float* add2[5];
    int mode[5];
    int M, N, K2p, ldc;
};

#define GBM 128
#define GBN 128
#define GBK 64
#define GSK 72
#define GSTAGE_ELEMS (128*GSK)
#define GSMEM_BYTES (4*GSTAGE_ELEMS*2)

__device__ __forceinline__ uint32_t smem_u32(const void* p) {
    return (uint32_t)__cvta_generic_to_shared(p);
}
__device__ __forceinline__ void ldsm4(uint32_t &r0, uint32_t &r1, uint32_t &r2, uint32_t &r3, uint32_t a) {
    asm volatile("ldmatrix.sync.aligned.m8n8.x4.shared.b16 {%0,%1,%2,%3}, [%4];\n"
        : "=r"(r0), "=r"(r1), "=r"(r2), "=r"(r3) : "r"(a));
}
__device__ __forceinline__ void mma_f16(float* c, const uint32_t* a, uint32_t b0, uint32_t b1) {
    asm volatile("mma.sync.aligned.m16n8k16.row.col.f32.f16.f16.f32 "
        "{%0,%1,%2,%3},{%4,%5,%6,%7},{%8,%9},{%0,%1,%2,%3};\n"
        : "+f"(c[0]), "+f"(c[1]), "+f"(c[2]), "+f"(c[3])
        : "r"(a[0]), "r"(a[1]), "r"(a[2]), "r"(a[3]), "r"(b0), "r"(b1));
}
__device__ __forceinline__ void cpasync16(uint32_t daddr, const void* src, int sbytes) {
    asm volatile("cp.async.cg.shared.global [%0], [%1], 16, %2;\n"
        :: "r"(daddr), "l"(src), "r"(sbytes));
}

__global__ __launch_bounds__(256, 2)
void bf16_gemm(MultiGemm g)
{
    extern __shared__ __half smem[];
    __half* sA = smem;
    __half* sB = smem + 2 * GSTAGE_ELEMS;

    int z = blockIdx.z;
    const __half* A  = g.A2;
    const __half* Bm = g.B2[z];
    float* C          = g.C[z];
    const float* bias = g.bias[z];
    const float* add1 = g.add1[z];
    const float* add2 = g.add2[z];
    int mode = g.mode[z];
    int M = g.M, N = g.N, K2p = g.K2p, ldc = g.ldc;

    int t = threadIdx.x, lane = t & 31, wid = t >> 5;
    int wm = wid & 1, wn = wid >> 1;
    int m0 = blockIdx.y * GBM, n0 = blockIdx.x * GBN;

    float acc[4][4][4];
#pragma unroll
    for (int i = 0; i < 4; i++)
#pragma unroll
        for (int j = 0; j < 4; j++)
#pragma unroll
            for (int c = 0; c < 4; c++) acc[i][j][c] = 0.f;

    int sel = lane >> 3, l7 = lane & 7;
    int ar = (sel & 1) * 8 + l7;
    int ac = (sel >> 1) * 8;
    int br = (sel >> 1) * 8 + l7;
    int bc = (sel & 1) * 8;

    int KT = K2p / GBK;

    auto loadStage = [&](int kt, int st) {
        int kbase = kt * GBK;
#pragma unroll
        for (int i = 0; i < 4; i++) {
            int idx = t + i * 256;
            int row = idx >> 3, sg = idx & 7;
            {
                int gr = m0 + row;
                int ok = (gr < M);
                const __half* src = A + (size_t)(ok ? gr : 0) * K2p + kbase + sg * 8;
                cpasync16(smem_u32(&sA[st * GSTAGE_ELEMS + row * GSK + sg * 8]), src, ok ? 16 : 0);
            }
            {
                int gr = n0 + row;
                int ok = (gr < N);
                const __half* src = Bm + (size_t)(ok ? gr : 0) * K2p + kbase + sg * 8;
                cpasync16(smem_u32(&sB[st * GSTAGE_ELEMS + row * GSK + sg * 8]), src, ok ? 16 : 0);
            }
        }
        asm volatile("cp.async.commit_group;\n");
    };

    loadStage(0, 0);

    for (int kt = 0; kt < KT; kt++) {
        int st = kt & 1;
        if (kt + 1 < KT) {
            loadStage(kt + 1, st ^ 1);
            asm volatile("cp.async.wait_group 1;\n");
        } else {
            asm volatile("cp.async.wait_group 0;\n");
        }
        __syncthreads();

        const __half* a_st = sA + st * GSTAGE_ELEMS;
        const __half* b_st = sB + st * GSTAGE_ELEMS;
#pragma unroll
        for (int kh = 0; kh < 4; kh++) {
            uint32_t af[4][4], bf[4][2];
#pragma unroll
            for (int mi = 0; mi < 4; mi++) {
                uint32_t addr = smem_u32(&a_st[(wm * 64 + mi * 16 + ar) * GSK + kh * 16 + ac]);
                ldsm4(af[mi][0], af[mi][1], af[mi][2], af[mi][3], addr);
            }
#pragma unroll
            for (int p = 0; p < 2; p++) {
                uint32_t r0, r1, r2, r3;
                uint32_t addr = smem_u32(&b_st[(wn * 32 + p * 16 + br) * GSK + kh * 16 + bc]);
                ldsm4(r0, r1, r2, r3, addr);
                bf[2*p][0] = r0; bf[2*p][1] = r1; bf[2*p+1][0] = r2; bf[2*p+1][1] = r3;
            }
#pragma unroll
            for (int mi = 0; mi < 4; mi++)
#pragma unroll
                for (int ni = 0; ni < 4; ni++)
                    mma_f16(acc[mi][ni], af[mi], bf[ni][0], bf[ni][1]);
        }
        __syncthreads();
    }

    int gq = lane >> 2, tig = lane & 3;
#pragma unroll
    for (int mi = 0; mi < 4; mi++) {
#pragma unroll
        for (int ni = 0; ni < 4; ni++) {
#pragma unroll
            for (int c = 0; c < 4; c++) {
                int row = m0 + wm * 64 + mi * 16 + gq + ((c >> 1) ? 8 : 0);
                int col = n0 + wn * 32 + ni * 8 + tig * 2 + (c & 1);
                if (row >= M || col >= N) continue;
                float v = acc[mi][ni][c];
                if (mode == 0) {
                    if (bias) v += bias[col];
                    C[(size_t)row * ldc + col] = v;
                } else if (mode == 2) {
                    v += add1[(size_t)row * ldc + col] + add2[(size_t)(row & 31) * ldc + col];
                    C[(size_t)row * ldc + col] = v;
                } else if (mode == 3) {
                    int b = row & 31, ti = row >> 5;
                    C[(size_t)b * (Tt * Vv) + (size_t)ti * Vv + col] = v;
                } else if (mode == 4) {
                    if (bias) v += bias[col];
                    int b = row & 31, ti = row >> 5;
                    C[((size_t)ti * Hh + col) * 32 + b] = v;
                } else { // 5
                    int b = row & 31;
                    float tv = tanhf(v);
                    C[(size_t)b * Hh + col] = tv;
                    ((float*)add1)[ptidx(col, b)] = tv;
                }
            }
        }
    }
}

// ---------------- maxout ----------------
__global__ void maxout_k(const float* __restrict__ tf, float* __restrict__ tm)
{
    int i = blockIdx.x * blockDim.x + threadIdx.x;
    int total = RT * Mm;
    if (i < total) {
        int r = i / Mm, m = i - r * Mm;
        tm[i] = fmaxf(tf[r * Hh + 2 * m], tf[r * Hh + 2 * m + 1]);
    }
}

// ================= persistent recurrence =================
__device__ __forceinline__ unsigned long long pack2(float2 v) {
    unsigned long long r;
    asm("mov.b64 %0, {%1, %2};" : "=l"(r) : "f"(v.x), "f"(v.y));
    return r;
}
__device__ __forceinline__ unsigned long long pack2f(float a, float b) {
    unsigned long long r;
    asm("mov.b64 %0, {%1, %2};" : "=l"(r) : "f"(a), "f"(b));
    return r;
}
__device__ __forceinline__ float2 unpack2(unsigned long long v) {
    float2 r;
    asm("mov.b64 {%0, %1}, %2;" : "=f"(r.x), "=f"(r.y) : "l"(v));
    return r;
}
__device__ __forceinline__ void ffma2(unsigned long long &acc, unsigned long long a, unsigned long long b) {
    asm("fma.rn.f32x2 %0, %1, %2, %0;" : "+l"(acc) : "l"(a), "l"(b));
}

__device__ __forceinline__ void gbar(unsigned &tgt) {
    __threadfence();
    __syncthreads();
    if (threadIdx.x == 0) {
        atomicAdd(&g_barctr, 1u);
        unsigned v;
        do {
            asm volatile("ld.acquire.gpu.global.u32 %0, [%1];" : "=r"(v) : "l"(&g_barctr) : "memory");
            if (v >= tgt) break;
            __nanosleep(16);
        } while (true);
    }
    __syncthreads();
    tgt += gridDim.x;
}

#define SMEM_RECUR (28352*4)

__global__ __launch_bounds__(256, 1)
void recur_persist(float* __restrict__ hT2, float* __restrict__ rhT2,
    const float* __restrict__ GUr, const float* __restrict__ GUz, const float* __restrict__ GUc,
    const float* __restrict__ Xr, const float* __restrict__ Xz, const float* __restrict__ Xc,
    const float* __restrict__ ctxR, const float* __restrict__ ctxZ, const float* __restrict__ ctxC,
    float* __restrict__ Sst, int nsteps)
{
    extern __shared__ float sm[];
    float* usr = sm;
    float* usz = sm + 8000;
    float* usc = sm + 16000;
    float* red = sm + 24000;
    float* zs  = sm + 28096;
    int tid = threadIdx.x, lane = tid & 31, w = tid >> 5;
    int jbase = blockIdx.x * NCOLS;

    for (int i4 = tid; i4 < 2000; i4 += 256) {
        int row = i4 / 250, k4 = (i4 % 250) * 4;
        *(float4*)(usr + row * 1000 + k4) = *(const float4*)(GUr + (size_t)(jbase + row) * 1000 + k4);
        *(float4*)(usz + row * 1000 + k4) = *(const float4*)(GUz + (size_t)(jbase + row) * 1000 + k4);
        *(float4*)(usc + row * 1000 + k4) = *(const float4*)(GUc + (size_t)(jbase + row) * 1000 + k4);
    }
    __syncthreads();

    // per-warp kk2 slices, all lens multiple of 4 (chunk-4, distance-3 buffering)
    const int offs[8] = {0, 64, 128, 192, 256, 320, 380, 440};
    const int lens[8] = {64, 64, 64, 64, 64, 60, 60, 60};
    int off = offs[w];
    int nch = lens[w] >> 2;
    unsigned tgt = gridDim.x;

    // ---- step-invariant epilogue mappings & ctx hoisting ----
    // phase A epilogue: outputs o = tid and o = tid+256
    int pA0 = tid >> 5,          bA0 = tid & 31;
    int pA1 = (tid + 256) >> 5,  bA1 = tid & 31;
    int colA0 = pA0 >> 1, gateA0 = pA0 & 1;
    int colA1 = pA1 >> 1, gateA1 = pA1 & 1;
    int jgA0 = jbase + colA0, jgA1 = jbase + colA1;
    const float* XA0 = gateA0 ? Xz : Xr;
    const float* XA1 = gateA1 ? Xz : Xr;
    float ctxA0 = 0.f, ctxA1 = 0.f, ctxB = 0.f;
    if (ctxR) {
        ctxA0 = (gateA0 ? ctxZ : ctxR)[jgA0 * 32 + bA0];
        ctxA1 = (gateA1 ? ctxZ : ctxR)[jgA1 * 32 + bA1];
    }
    // phase B epilogue: one output per thread
    int colB = tid >> 5, bB = tid & 31;
    int jgB = jbase + colB;
    if (ctxC) ctxB = ctxC[jgB * 32 + bB];

    for (int step = 0; step < nsteps; step++) {
        // early per-step input loads (used in epilogues; ~2000 cyc to complete)
        float xA0 = XA0[((size_t)step * Hh + jgA0) * 32 + bA0];
        float xA1 = XA1[((size_t)step * Hh + jgA1) * 32 + bA1];
        float xB  = Xc [((size_t)step * Hh + jgB ) * 32 + bB ];

        // ---------- phase A: r,z gates ----------
        {
            unsigned long long acc[16];
#pragma unroll
            for (int p = 0; p < 16; p++) acc[p] = 0ull;
            float2 c0[4], c1[4], c2[4], c3[4];
#pragma unroll
            for (int q = 0; q < 4; q++) c0[q] = *(const float2*)(hT2 + (off + q) * 64 + 2 * lane);
#pragma unroll
            for (int q = 0; q < 4; q++) c1[q] = *(const float2*)(hT2 + (off + 4 + q) * 64 + 2 * lane);
#pragma unroll
            for (int q = 0; q < 4; q++) c2[q] = *(const float2*)(hT2 + (off + 8 + q) * 64 + 2 * lane);
            for (int ch = 0; ch < nch; ch++) {
                if (ch + 3 < nch) {
#pragma unroll
                    for (int q = 0; q < 4; q++)
                        c3[q] = *(const float2*)(hT2 + (off + (ch + 3) * 4 + q) * 64 + 2 * lane);
                }
#pragma unroll
                for (int q2 = 0; q2 < 4; q2 += 2) {
                    int k0 = (off + ch * 4 + q2) * 2;
                    unsigned long long h0p = pack2(c0[q2]), h1p = pack2(c0[q2 + 1]);
#pragma unroll
                    for (int p = 0; p < 16; p++) {
                        const float* us = (p & 1) ? usz : usr;
                        float4 u = *(const float4*)(us + (p >> 1) * 1000 + k0);
                        ffma2(acc[p], h0p, pack2f(u.x, u.y));
                        ffma2(acc[p], h1p, pack2f(u.z, u.w));
                    }
                }
#pragma unroll
                for (int q = 0; q < 4; q++) { c0[q] = c1[q]; c1[q] = c2[q]; c2[q] = c3[q]; }
            }
#pragma unroll
            for (int p = 0; p < 16; p++) {
                float2 a = unpack2(acc[p]);
                red[w * 512 + p * 32 + lane] = a.x + a.y;
            }
            __syncthreads();
            // epilogue: two outputs, preloaded X/ctx
            {
                float s0 = 0.f, s1 = 0.f;
#pragma unroll
                for (int ww = 0; ww < 8; ww++) s0 += red[ww * 512 + pA0 * 32 + bA0];
#pragma unroll
                for (int ww = 0; ww < 8; ww++) s1 += red[ww * 512 + pA1 * 32 + bA1];
                float pre0 = xA0 + s0 + ctxA0;
                float pre1 = xA1 + s1 + ctxA1;
                float sg0 = 1.f / (1.f + __expf(-pre0));
                float sg1 = 1.f / (1.f + __expf(-pre1));
                if (gateA0 == 0) { int hi = ptidx(jgA0, bA0); rhT2[hi] = sg0 * hT2[hi]; }
                else             { zs[colA0 * 32 + bA0] = sg0; }
                if (gateA1 == 0) { int hi = ptidx(jgA1, bA1); rhT2[hi] = sg1 * hT2[hi]; }
                else             { zs[colA1 * 32 + bA1] = sg1; }
            }
        }
        gbar(tgt);
        // ---------- phase B: candidate + blend ----------
        {
            unsigned long long acc[8];
#pragma unroll
            for (int p = 0; p < 8; p++) acc[p] = 0ull;
            float2 c0[4], c1[4], c2[4], c3[4];
#pragma unroll
            for (int q = 0; q < 4; q++) c0[q] = *(const float2*)(rhT2 + (off + q) * 64 + 2 * lane);
#pragma unroll
            for (int q = 0; q < 4; q++) c1[q] = *(const float2*)(rhT2 + (off + 4 + q) * 64 + 2 * lane);
#pragma unroll
            for (int q = 0; q < 4; q++) c2[q] = *(const float2*)(rhT2 + (off + 8 + q) * 64 + 2 * lane);
            for (int ch = 0; ch < nch; ch++) {
                if (ch + 3 < nch) {
#pragma unroll
                    for (int q = 0; q < 4; q++)
                        c3[q] = *(const float2*)(rhT2 + (off + (ch + 3) * 4 + q) * 64 + 2 * lane);
                }
#pragma unroll
                for (int q2 = 0; q2 < 4; q2 += 2) {
                    int k0 = (off + ch * 4 + q2) * 2;
                    unsigned long long h0p = pack2(c0[q2]), h1p = pack2(c0[q2 + 1]);
#pragma unroll
                    for (int p = 0; p < 8; p++) {
                        float4 u = *(const float4*)(usc + p * 1000 + k0);
                        ffma2(acc[p], h0p, pack2f(u.x, u.y));
                        ffma2(acc[p], h1p, pack2f(u.z, u.w));
                    }
                }
#pragma unroll
                for (int q = 0; q < 4; q++) { c0[q] = c1[q]; c1[q] = c2[q]; c2[q] = c3[q]; }
            }
            __syncthreads();
#pragma unroll
            for (int p = 0; p < 8; p++) {
                float2 a = unpack2(acc[p]);
                red[w * 256 + p * 32 + lane] = a.x + a.y;
            }
            __syncthreads();
            {
                float s = 0.f;
#pragma unroll
                for (int ww = 0; ww < 8; ww++) s += red[ww * 256 + colB * 32 + bB];
                float pre = xB + s + ctxB;
                float cand = tanhf(pre);
                float zv = zs[colB * 32 + bB];
                int hi = ptidx(jgB, bB);
                float hv = hT2[hi];
                float hn = (1.f - zv) * hv + zv * cand;
                hT2[hi] = hn;
                if (Sst != nullptr && step + 1 < nsteps)
                    Sst[((size_t)(step + 1) * 32 + bB) * Hh + jgB] = hn;
            }
        }
        gbar(tgt);
    }
}

// ---------------- host orchestration ----------------
extern "C" void kernel_launch(void* const* d_in, const int* in_sizes, int n_in,
                              void* d_out, int out_size)
{
    const int*   src     = (const int*)d_in[0];
    const int*   tgt     = (const int*)d_in[1];
    const float* src_emb = (const float*)d_in[3];
    const float* tgt_emb = (const float*)d_in[4];
    const float* enc_W   = (const float*)d_in[5];
    const float* enc_Wz  = (const float*)d_in[6];
    const float* enc_Wr  = (const float*)d_in[7];
    const float* enc_U   = (const float*)d_in[8];
    const float* enc_Uz  = (const float*)d_in[9];
    const float* enc_Ur  = (const float*)d_in[10];
    const float* enc_b   = (const float*)d_in[11];
    const float* enc_bz  = (const float*)d_in[12];
    const float* enc_br  = (const float*)d_in[13];
    const float* dec_W   = (const float*)d_in[14];
    const float* dec_Wz  = (const float*)d_in[15];
    const float* dec_Wr  = (const float*)d_in[16];
    const float* dec_U   = (const float*)d_in[17];
    const float* dec_Uz  = (const float*)d_in[18];
    const float* dec_Ur  = (const float*)d_in[19];
    const float* dec_C   = (const float*)d_in[20];
    const float* dec_Cz  = (const float*)d_in[21];
    const float* dec_Cr  = (const float*)d_in[22];
    const float* dec_b   = (const float*)d_in[23];
    const float* dec_bz  = (const float*)d_in[24];
    const float* dec_br  = (const float*)d_in[25];
    const float* W_s     = (const float*)d_in[26];
    const float* U_o     = (const float*)d_in[27];
    const float* V_o     = (const float*)d_in[28];
    const float* C_o     = (const float*)d_in[29];
    const float* W_o     = (const float*)d_in[30];
    float* out = (float*)d_out;

    float *Xr, *Xz, *Xc, *Yr, *Yz, *Yc, *Yo;
    float *hT2, *s0T, *rhT2, *cCrT, *cCzT, *cCT, *cCo, *Sst, *tfull, *tmax;
    unsigned* barctr;
    cudaGetSymbolAddress((void**)&Xr, g_Xr);
    cudaGetSymbolAddress((void**)&Xz, g_Xz);
    cudaGetSymbolAddress((void**)&Xc, g_Xc);
    cudaGetSymbolAddress((void**)&Yr, g_Yr);
    cudaGetSymbolAddress((void**)&Yz, g_Yz);
    cudaGetSymbolAddress((void**)&Yc, g_Yc);
    cudaGetSymbolAddress((void**)&Yo, g_Yo);
    cudaGetSymbolAddress((void**)&hT2, g_hT2);
    cudaGetSymbolAddress((void**)&s0T, g_s0T);
    cudaGetSymbolAddress((void**)&rhT2, g_rhT2);
    cudaGetSymbolAddress((void**)&cCrT, g_cCrT);
    cudaGetSymbolAddress((void**)&cCzT, g_cCzT);
    cudaGetSymbolAddress((void**)&cCT,  g_cCT);
    cudaGetSymbolAddress((void**)&cCo, g_cCo);
    cudaGetSymbolAddress((void**)&Sst, g_S);
    cudaGetSymbolAddress((void**)&tfull, g_tfull);
    cudaGetSymbolAddress((void**)&tmax, g_tmax);
    cudaGetSymbolAddress((void**)&barctr, g_barctr);

    __half *eWr2, *eWz2, *eW2, *dWr2, *dWz2, *dW2, *Vo2;
    __half *Ws2, *Cr2, *Cz2, *C2, *Co2, *Uo2, *Wo2;
    __half *X2, *Y2, *cT2, *S2, *T2;
    cudaGetSymbolAddress((void**)&eWr2, g2_eWr);
    cudaGetSymbolAddress((void**)&eWz2, g2_eWz);
    cudaGetSymbolAddress((void**)&eW2,  g2_eW);
    cudaGetSymbolAddress((void**)&dWr2, g2_dWr);
    cudaGetSymbolAddress((void**)&dWz2, g2_dWz);
    cudaGetSymbolAddress((void**)&dW2,  g2_dW);
    cudaGetSymbolAddress((void**)&Vo2,  g2_Vo);
    cudaGetSymbolAddress((void**)&Ws2,  g2_Ws);
    cudaGetSymbolAddress((void**)&Cr2,  g2_Cr);
    cudaGetSymbolAddress((void**)&Cz2,  g2_Cz);
    cudaGetSymbolAddress((void**)&C2,   g2_C);
    cudaGetSymbolAddress((void**)&Co2,  g2_Co);
    cudaGetSymbolAddress((void**)&Uo2,  g2_Uo);
    cudaGetSymbolAddress((void**)&Wo2,  g2_Wo);
    cudaGetSymbolAddress((void**)&X2,   g2_X);
    cudaGetSymbolAddress((void**)&Y2,   g2_Y);
    cudaGetSymbolAddress((void**)&cT2,  g2_cT);
    cudaGetSymbolAddress((void**)&S2,   g2_S);
    cudaGetSymbolAddress((void**)&T2,   g2_T);

    cudaFuncSetAttribute(recur_persist, cudaFuncAttributeMaxDynamicSharedMemorySize, SMEM_RECUR);
    cudaFuncSetAttribute(bf16_gemm, cudaFuncAttributeMaxDynamicSharedMemorySize, GSMEM_BYTES);

    // ---- weight converts ----
    {
        ConvBatch cb = {};
        const float* s[7] = {enc_Wr, enc_Wz, enc_W, dec_Wr, dec_Wz, dec_W, V_o};
        __half* d[7] = {eWr2, eWz2, eW2, dWr2, dWz2, dW2, Vo2};
        for (int i = 0; i < 7; i++) cb.e[i] = {s[i], d[i], Hh, Ee, K2E, 1, 0};
        int total = Hh * (K2E / 8);
        dim3 gr((total + 255) / 256, 7);
        conv_k<<<gr, 256>>>(cb);
    }
    {
        ConvBatch cb = {};
        const float* s[6] = {W_s, dec_Cr, dec_Cz, dec_C, C_o, U_o};
        __half* d[6] = {Ws2, Cr2, Cz2, C2, Co2, Uo2};
        for (int i = 0; i < 6; i++) cb.e[i] = {s[i], d[i], Hh, Hh, K2H, 1, 0};
        int total = Hh * (K2H / 8);
        dim3 gr((total + 255) / 256, 6);
        conv_k<<<gr, 256>>>(cb);
    }
    {
        ConvBatch cb = {};
        cb.e[0] = {W_o, Wo2, Vv, Mm, K2M, 1, 0};
        int total = Vv * (K2M / 8);
        dim3 gr((total + 255) / 256, 1);
        conv_k<<<gr, 256>>>(cb);
    }

    // ---- fused gathers ----
    gather_trip<<<RS, 128>>>(src, src_emb, X2, Ss);
    gather_trip<<<RT, 128>>>(tgt, tgt_emb, Y2, Tt);

    // ---- input projections ----
    {
        MultiGemm g = {};
        g.A2 = X2; g.M = RS; g.N = Hh; g.K2p = K2E; g.ldc = Hh;
        g.B2[0] = eWr2; g.C[0] = Xr; g.bias[0] = enc_br; g.mode[0] = 4;
        g.B2[1] = eWz2; g.C[1] = Xz; g.bias[1] = enc_bz; g.mode[1] = 4;
        g.B2[2] = eW2;  g.C[2] = Xc; g.bias[2] = enc_b;  g.mode[2] = 4;
        dim3 gr((Hh + GBN - 1) / GBN, (RS + GBM - 1) / GBM, 3);
        bf16_gemm<<<gr, 256, GSMEM_BYTES>>>(g);
    }
    {
        MultiGemm g = {};
        g.A2 = Y2; g.M = RT; g.N = Hh; g.K2p = K2E; g.ldc = Hh;
        g.B2[0] = dWr2; g.C[0] = Yr; g.bias[0] = dec_br; g.mode[0] = 4;
        g.B2[1] = dWz2; g.C[1] = Yz; g.bias[1] = dec_bz; g.mode[1] = 4;
        g.B2[2] = dW2;  g.C[2] = Yc; g.bias[2] = dec_b;  g.mode[2] = 4;
        g.B2[3] = Vo2;  g.C[3] = Yo; g.bias[3] = nullptr; g.mode[3] = 0;
        dim3 gr((Hh + GBN - 1) / GBN, (RT + GBM - 1) / GBM, 4);
        bf16_gemm<<<gr, 256, GSMEM_BYTES>>>(g);
    }

    // ---- encoder recurrence ----
    cudaMemsetAsync(hT2, 0, (size_t)Hh * Bb * sizeof(float));
    cudaMemsetAsync(barctr, 0, sizeof(unsigned));
    recur_persist<<<NBLK, 256, SMEM_RECUR>>>(hT2, rhT2,
        enc_Ur, enc_Uz, enc_U, Xr, Xz, Xc,
        nullptr, nullptr, nullptr, nullptr, Ss);

    // ---- context projections ----
    {
        ConvBatch cb = {};
        cb.e[0] = {hT2, cT2, Bb, Hh, K2H, 0, 1};
        int total = Bb * (K2H / 8);
        dim3 gr((total + 255) / 256, 1);
        conv_k<<<gr, 256>>>(cb);
    }
    {
        MultiGemm g = {};
        g.A2 = cT2; g.M = Bb; g.N = Hh; g.K2p = K2H; g.ldc = Hh;
        g.B2[0] = Ws2; g.C[0] = Sst;  g.add1[0] = s0T; g.mode[0] = 5;
        g.B2[1] = Cr2; g.C[1] = cCrT; g.mode[1] = 4;
        g.B2[2] = Cz2; g.C[2] = cCzT; g.mode[2] = 4;
        g.B2[3] = C2;  g.C[3] = cCT;  g.mode[3] = 4;
        g.B2[4] = Co2; g.C[4] = cCo;  g.mode[4] = 0;
        dim3 gr((Hh + GBN - 1) / GBN, 1, 5);
        bf16_gemm<<<gr, 256, GSMEM_BYTES>>>(g);
    }

    // ---- decoder recurrence ----
    cudaMemsetAsync(barctr, 0, sizeof(unsigned));
    recur_persist<<<NBLK, 256, SMEM_RECUR>>>(s0T, rhT2,
        dec_Ur, dec_Uz, dec_U, Yr, Yz, Yc,
        cCrT, cCzT, cCT, Sst, Tt);

    // ---- output layer ----
    {
        ConvBatch cb = {};
        cb.e[0] = {Sst, S2, RT, Hh, K2H, 0, 0};
        int total = RT * (K2H / 8);
        dim3 gr((total + 255) / 256, 1);
        conv_k<<<gr, 256>>>(cb);
    }
    {
        MultiGemm g = {};
        g.A2 = S2; g.M = RT; g.N = Hh; g.K2p = K2H; g.ldc = Hh;
        g.B2[0] = Uo2; g.C[0] = tfull; g.add1[0] = Yo; g.add2[0] = cCo; g.mode[0] = 2;
        dim3 gr((Hh + GBN - 1) / GBN, (RT + GBM - 1) / GBM, 1);
        bf16_gemm<<<gr, 256, GSMEM_BYTES>>>(g);
    }
    maxout_k<<<(RT * Mm + 255) / 256, 256>>>(tfull, tmax);
    {
        ConvBatch cb = {};
        cb.e[0] = {tmax, T2, RT, Mm, K2M, 0, 0};
        int total = RT * (K2M / 8);
        dim3 gr((total + 255) / 256, 1);
        conv_k<<<gr, 256>>>(cb);
    }
    {
        MultiGemm g = {};
        g.A2 = T2; g.M = RT; g.N = Vv; g.K2p = K2M; g.ldc = Vv;
        g.B2[0] = Wo2; g.C[0] = out; g.mode[0] = 3;
        dim3 gr((Vv + GBN - 1) / GBN, (RT + GBM - 1) / GBM, 1);
        bf16_gemm<<<gr, 256, GSMEM_BYTES>>>(g);
    }
}